// round 11
// baseline (speedup 1.0000x reference)
#include <cuda_runtime.h>
#include <cuda_bf16.h>
#include <cstdint>
#include <math.h>

#define BB 2
#define SS 2048
#define EE 2048
#define HH 16
#define DD 128
#define MROWS (BB*SS)   // 4096

// ---------------- device scratch ----------------
__device__ __nv_bfloat16 g_Qh[MROWS*EE];  // [B*H, S, D]
__device__ __nv_bfloat16 g_Ql[MROWS*EE];
__device__ __nv_bfloat16 g_Kh[MROWS*EE];
__device__ __nv_bfloat16 g_Kl[MROWS*EE];
__device__ __nv_bfloat16 g_Vh[MROWS*EE];  // [B*H, D, S]
__device__ __nv_bfloat16 g_Vl[MROWS*EE];
__device__ __nv_bfloat16 g_X1h[MROWS*EE];
__device__ __nv_bfloat16 g_X1l[MROWS*EE];
__device__ __nv_bfloat16 g_X2h[MROWS*EE];
__device__ __nv_bfloat16 g_X2l[MROWS*EE];
__device__ __nv_bfloat16 g_X3h[MROWS*EE];
__device__ __nv_bfloat16 g_X3l[MROWS*EE];
__device__ __nv_bfloat16 g_Wth[4*EE*EE];
__device__ __nv_bfloat16 g_Wtl[4*EE*EE];

// ---------------- primitives ----------------
__device__ __forceinline__ uint32_t smem_u32(const void* p) {
    uint32_t a;
    asm("{ .reg .u64 t; cvta.to.shared.u64 t, %1; cvt.u32.u64 %0, t; }" : "=r"(a) : "l"(p));
    return a;
}
#define CP_ASYNC_16(dst_u32, src_ptr) \
    asm volatile("cp.async.cg.shared.global [%0], [%1], 16;" :: "r"(dst_u32), "l"(src_ptr))
#define CP_COMMIT() asm volatile("cp.async.commit_group;" ::: "memory")
#define CP_WAIT(n)  asm volatile("cp.async.wait_group %0;" :: "n"(n) : "memory")

// NOTE: NOT volatile — pure register op; lets nvcc/ptxas schedule & pipeline
// HMMAs freely. Data dependences via "+f" still enforce per-accumulator order.
__device__ __forceinline__ void mma16816(float* c, const uint32_t* a, const uint32_t* b) {
    asm("mma.sync.aligned.m16n8k16.row.col.f32.bf16.bf16.f32 "
        "{%0,%1,%2,%3}, {%4,%5,%6,%7}, {%8,%9}, {%0,%1,%2,%3};"
        : "+f"(c[0]), "+f"(c[1]), "+f"(c[2]), "+f"(c[3])
        : "r"(a[0]), "r"(a[1]), "r"(a[2]), "r"(a[3]), "r"(b[0]), "r"(b[1]));
}

__device__ __forceinline__ void ldsm_x4(uint32_t& r0, uint32_t& r1, uint32_t& r2,
                                        uint32_t& r3, uint32_t addr) {
    asm volatile("ldmatrix.sync.aligned.m8n8.x4.shared.b16 {%0,%1,%2,%3}, [%4];"
                 : "=r"(r0), "=r"(r1), "=r"(r2), "=r"(r3) : "r"(addr));
}

__device__ __forceinline__ uint32_t pack_split(float x, float y, uint32_t& lo) {
    __nv_bfloat162 hp, lp;
    hp.x = __float2bfloat16(x);
    hp.y = __float2bfloat16(y);
    lp.x = __float2bfloat16(x - __bfloat162float(hp.x));
    lp.y = __float2bfloat16(y - __bfloat162float(hp.y));
    lo = *(uint32_t*)&lp;
    return *(uint32_t*)&hp;
}

// ---------------------------------------------------------------------------
// Merged conversion kernels
// ---------------------------------------------------------------------------
__global__ __launch_bounds__(256)
void split3_kernel(const float* __restrict__ X0, const float* __restrict__ X1,
                   const float* __restrict__ X2,
                   __nv_bfloat16* __restrict__ H0, __nv_bfloat16* __restrict__ L0,
                   __nv_bfloat16* __restrict__ H1, __nv_bfloat16* __restrict__ L1,
                   __nv_bfloat16* __restrict__ H2, __nv_bfloat16* __restrict__ L2,
                   int n4)
{
    const int z = blockIdx.y;
    const float* X = (z == 0) ? X0 : (z == 1) ? X1 : X2;
    __nv_bfloat16* H = (z == 0) ? H0 : (z == 1) ? H1 : H2;
    __nv_bfloat16* L = (z == 0) ? L0 : (z == 1) ? L1 : L2;
    int i = blockIdx.x * blockDim.x + threadIdx.x;
    const int stride = gridDim.x * blockDim.x;
    for (; i < n4; i += stride) {
        float4 v = ((const float4*)X)[i];
        uint32_t l0, l1;
        uint32_t h0 = pack_split(v.x, v.y, l0);
        uint32_t h1 = pack_split(v.z, v.w, l1);
        ((uint32_t*)H)[2*i]   = h0;
        ((uint32_t*)H)[2*i+1] = h1;
        ((uint32_t*)L)[2*i]   = l0;
        ((uint32_t*)L)[2*i+1] = l1;
    }
}

__global__ __launch_bounds__(1024)
void transpose4_kernel(const float* __restrict__ W0, const float* __restrict__ W1,
                       const float* __restrict__ W2, const float* __restrict__ W3,
                       __nv_bfloat16* __restrict__ Th, __nv_bfloat16* __restrict__ Tl)
{
    __shared__ float t[32][33];
    const int z = blockIdx.z;
    const float* W = (z == 0) ? W0 : (z == 1) ? W1 : (z == 2) ? W2 : W3;
    __nv_bfloat16* TH = Th + (size_t)z * EE * EE;
    __nv_bfloat16* TL = Tl + (size_t)z * EE * EE;
    const int n0 = blockIdx.x * 32, k0 = blockIdx.y * 32;
    const int tx = threadIdx.x, ty = threadIdx.y;
    t[ty][tx] = W[(size_t)(k0 + ty) * EE + n0 + tx];
    __syncthreads();
    float v = t[tx][ty];
    const int n = n0 + ty, k = k0 + tx;
    __nv_bfloat16 h = __float2bfloat16(v);
    TH[(size_t)n * EE + k] = h;
    TL[(size_t)n * EE + k] = __float2bfloat16(v - __bfloat162float(h));
}

// ---------------------------------------------------------------------------
// Split-bf16 mma.sync GEMM with ldmatrix fragment loads.
// R8 geometry: BM=128, BN=256, BK=32, 2-stage, 8 warps (2x4), warp 64x64.
// Term-major MMA order: 32 independent HMMAs between accumulator reuses.
// ---------------------------------------------------------------------------
#define BM 128
#define BN 256
#define BK 32
#define ROWB 112                       // 64B data + 48B pad (conflict-free LDSM)
#define A_BYTES (BM*ROWB)              // 14336
#define B_BYTES (BN*ROWB)              // 28672
#define STAGE_BYTES (2*A_BYTES + 2*B_BYTES)   // 86016
#define GEMM_SMEM (2*STAGE_BYTES)             // 172032

template<int MODE>
__global__ __launch_bounds__(256)
void gemm_mma_kernel(const __nv_bfloat16* __restrict__ Xh, const __nv_bfloat16* __restrict__ Xl,
                     const __nv_bfloat16* __restrict__ Wh, const __nv_bfloat16* __restrict__ Wl,
                     const float* __restrict__ bias, float* __restrict__ Yf,
                     __nv_bfloat16* __restrict__ Yh, __nv_bfloat16* __restrict__ Yl)
{
    extern __shared__ char sm[];
    const int tid  = threadIdx.x;
    const int lane = tid & 31;
    const int wid  = tid >> 5;
    const int g    = lane >> 2;
    const int tig  = lane & 3;

    const int m0 = blockIdx.y * BM;
    const int n0 = blockIdx.x * BN;
    const int wm = (wid & 1) * 64;
    const int wn = (wid >> 1) * 64;

    const uint32_t smb = smem_u32(sm);
    const uint32_t lrow = (lane & 15);
    const uint32_t lcol = (lane >> 4) * 16;

    float c[4][8][4];
#pragma unroll
    for (int i = 0; i < 4; i++)
#pragma unroll
        for (int j = 0; j < 8; j++)
#pragma unroll
            for (int q = 0; q < 4; q++) c[i][j][q] = 0.f;

    const __nv_bfloat16* srcA[2] = { Xh + (size_t)m0*EE, Xl + (size_t)m0*EE };
    const __nv_bfloat16* srcB[2] = { Wh + (size_t)n0*EE, Wl + (size_t)n0*EE };

    auto load_stage = [&](int s) {
        const int buf = s & 1;
        const uint32_t base = smb + buf * STAGE_BYTES;
        const int k0 = s * BK;
#pragma unroll
        for (int v = 0; v < 2; v++) {
            const __nv_bfloat16* src = srcA[v] + k0;
            const uint32_t dst0 = base + v * A_BYTES;
#pragma unroll
            for (int i = 0; i < 2; i++) {
                int idx = tid + i * 256;           // 0..511
                int r = idx >> 2, ch = idx & 3;
                CP_ASYNC_16(dst0 + r * ROWB + ch * 16, src + (size_t)r * EE + ch * 8);
            }
        }
#pragma unroll
        for (int v = 0; v < 2; v++) {
            const __nv_bfloat16* src = srcB[v] + k0;
            const uint32_t dst0 = base + 2 * A_BYTES + v * B_BYTES;
#pragma unroll
            for (int i = 0; i < 4; i++) {
                int idx = tid + i * 256;           // 0..1023
                int r = idx >> 2, ch = idx & 3;
                CP_ASYNC_16(dst0 + r * ROWB + ch * 16, src + (size_t)r * EE + ch * 8);
            }
        }
        CP_COMMIT();
    };

    const int NS = EE / BK;   // 64
    load_stage(0);

    for (int s = 0; s < NS; s++) {
        const int buf = s & 1;
        if (s + 1 < NS) { load_stage(s + 1); CP_WAIT(1); }
        else            { CP_WAIT(0); }
        __syncthreads();

        const uint32_t Ah = smb + buf * STAGE_BYTES;
        const uint32_t Al = Ah + A_BYTES;
        const uint32_t Bh = Ah + 2 * A_BYTES;
        const uint32_t Bl = Bh + B_BYTES;

#pragma unroll
        for (int kb = 0; kb < BK; kb += 16) {
            const uint32_t kbyte = kb * 2 + lcol;
            uint32_t ah[4][4], al[4][4], bh[8][2], bl[8][2];
#pragma unroll
            for (int mt = 0; mt < 4; mt++) {
                const uint32_t ro = (wm + mt * 16 + lrow) * ROWB + kbyte;
                ldsm_x4(ah[mt][0], ah[mt][1], ah[mt][2], ah[mt][3], Ah + ro);
                ldsm_x4(al[mt][0], al[mt][1], al[mt][2], al[mt][3], Al + ro);
            }
#pragma unroll
            for (int np = 0; np < 4; np++) {
                const uint32_t ro = (wn + np * 16 + lrow) * ROWB + kbyte;
                uint32_t h0, h1, h2, h3, L0, L1, L2, L3;
                ldsm_x4(h0, h1, h2, h3, Bh + ro);
                ldsm_x4(L0, L1, L2, L3, Bl + ro);
                bh[2*np][0] = h0; bh[2*np][1] = h2;
                bh[2*np+1][0] = h1; bh[2*np+1][1] = h3;
                bl[2*np][0] = L0; bl[2*np][1] = L2;
                bl[2*np+1][0] = L1; bl[2*np+1][1] = L3;
            }
            // term-major: 32 independent MMAs between accumulator reuses
#pragma unroll
            for (int mt = 0; mt < 4; mt++)
#pragma unroll
                for (int nt = 0; nt < 8; nt++)
                    mma16816(c[mt][nt], ah[mt], bh[nt]);
#pragma unroll
            for (int mt = 0; mt < 4; mt++)
#pragma unroll
                for (int nt = 0; nt < 8; nt++)
                    mma16816(c[mt][nt], ah[mt], bl[nt]);
#pragma unroll
            for (int mt = 0; mt < 4; mt++)
#pragma unroll
                for (int nt = 0; nt < 8; nt++)
                    mma16816(c[mt][nt], al[mt], bh[nt]);
        }
        __syncthreads();
    }

    // ---- epilogue ----
#pragma unroll
    for (int mt = 0; mt < 4; mt++) {
        const int m = m0 + wm + mt * 16 + g;
        const int bI = m >> 11;
        const int sI = m & (SS - 1);
#pragma unroll
        for (int nt = 0; nt < 8; nt++) {
            const int n = n0 + wn + nt * 8 + 2 * tig;
            const float b0 = bias[n], b1 = bias[n + 1];
            const float y0 = c[mt][nt][0] + b0, y1 = c[mt][nt][1] + b1;
            const float y2 = c[mt][nt][2] + b0, y3 = c[mt][nt][3] + b1;
            if (MODE == 0) {
                size_t o0 = (size_t)m * EE + n;
                float2 v0; v0.x = y0; v0.y = y1;
                float2 v1; v1.x = y2; v1.y = y3;
                *(float2*)&Yf[o0] = v0;
                *(float2*)&Yf[o0 + 8 * EE] = v1;
            } else if (MODE == 1) {
                const int h = n >> 7, d = n & 127;
                size_t o0 = (((size_t)(bI * HH + h) * SS + sI) * DD) + d;
                uint32_t lo, hi;
                hi = pack_split(y0, y1, lo);
                *(uint32_t*)&Yh[o0] = hi; *(uint32_t*)&Yl[o0] = lo;
                hi = pack_split(y2, y3, lo);
                *(uint32_t*)&Yh[o0 + 8 * DD] = hi; *(uint32_t*)&Yl[o0 + 8 * DD] = lo;
            } else {
                const int h = n >> 7, d = n & 127;
                const size_t base = (size_t)(bI * HH + h) * DD;
                size_t o00 = (base + d) * SS + sI;
                size_t o01 = (base + d + 1) * SS + sI;
                __nv_bfloat16 t;
                t = __float2bfloat16(y0); Yh[o00] = t;
                Yl[o00] = __float2bfloat16(y0 - __bfloat162float(t));
                t = __float2bfloat16(y1); Yh[o01] = t;
                Yl[o01] = __float2bfloat16(y1 - __bfloat162float(t));
                t = __float2bfloat16(y2); Yh[o00 + 8] = t;
                Yl[o00 + 8] = __float2bfloat16(y2 - __bfloat162float(t));
                t = __float2bfloat16(y3); Yh[o01 + 8] = t;
                Yl[o01 + 8] = __float2bfloat16(y3 - __bfloat162float(t));
            }
        }
    }
}

// ---------------------------------------------------------------------------
// Flash attention, split-bf16 mma.sync + ldmatrix, double-buffered K/V.
// MMAs non-volatile; score/PV issue order interleaves the two tiles per pair.
// ---------------------------------------------------------------------------
#define AQT 128
#define AKT 64
#define ROWK 272
#define ROWV 144
#define KH_BYTES (64*ROWK)
#define VH_BYTES (128*ROWV)
#define KV_STAGE (2*KH_BYTES + 2*VH_BYTES)
#define ATTN_SMEM (2*KV_STAGE)

__global__ __launch_bounds__(256)
void attn_mma_kernel(const __nv_bfloat16* __restrict__ Qh_, const __nv_bfloat16* __restrict__ Ql_,
                     const __nv_bfloat16* __restrict__ Kh_, const __nv_bfloat16* __restrict__ Kl_,
                     const __nv_bfloat16* __restrict__ Vh_, const __nv_bfloat16* __restrict__ Vl_,
                     __nv_bfloat16* __restrict__ Xh, __nv_bfloat16* __restrict__ Xl)
{
    extern __shared__ char sm[];
    const uint32_t smb = smem_u32(sm);
    const int tid  = threadIdx.x;
    const int lane = tid & 31;
    const int wid  = tid >> 5;
    const int g    = lane >> 2;
    const int tig  = lane & 3;
    const uint32_t lrow = (lane & 15);
    const uint32_t lcol = (lane >> 4) * 16;

    const int bh = blockIdx.y;
    const int q0 = blockIdx.x * AQT;
    const size_t hoff = (size_t)bh * SS * DD;

    const __nv_bfloat16* ksrc[2] = { Kh_ + hoff, Kl_ + hoff };
    const __nv_bfloat16* vsrc[2] = { Vh_ + (size_t)bh * DD * SS, Vl_ + (size_t)bh * DD * SS };

    {
        const __nv_bfloat16* qsrc[2] = { Qh_ + hoff + (size_t)q0 * DD,
                                         Ql_ + hoff + (size_t)q0 * DD };
#pragma unroll
        for (int v = 0; v < 2; v++) {
            const uint32_t dst0 = smb + v * (128 * ROWK);
#pragma unroll
            for (int i = 0; i < 8; i++) {
                int idx = tid + i * 256;
                int row = idx >> 4, ch = idx & 15;
                CP_ASYNC_16(dst0 + row * ROWK + ch * 16, qsrc[v] + (size_t)row * DD + ch * 8);
            }
        }
        CP_COMMIT(); CP_WAIT(0);
        __syncthreads();
    }

    uint32_t qh[8][4], ql[8][4];
    {
        const uint32_t ro = (wid * 16 + lrow) * ROWK + lcol;
#pragma unroll
        for (int ks = 0; ks < 8; ks++) {
            ldsm_x4(qh[ks][0], qh[ks][1], qh[ks][2], qh[ks][3], smb + ro + ks * 32);
            ldsm_x4(ql[ks][0], ql[ks][1], ql[ks][2], ql[ks][3],
                    smb + 128 * ROWK + ro + ks * 32);
        }
    }
    __syncthreads();

    auto load_kv = [&](int it) {
        const uint32_t base = smb + (it & 1) * KV_STAGE;
        const int kt = it * AKT;
#pragma unroll
        for (int v = 0; v < 2; v++) {
            const uint32_t dst0 = base + v * KH_BYTES;
#pragma unroll
            for (int i = 0; i < 4; i++) {
                int idx = tid + i * 256;
                int row = idx >> 4, ch = idx & 15;
                CP_ASYNC_16(dst0 + row * ROWK + ch * 16,
                            ksrc[v] + (size_t)(kt + row) * DD + ch * 8);
            }
        }
#pragma unroll
        for (int v = 0; v < 2; v++) {
            const uint32_t dst0 = base + 2 * KH_BYTES + v * VH_BYTES;
#pragma unroll
            for (int i = 0; i < 4; i++) {
                int idx = tid + i * 256;
                int row = idx >> 3, ch = idx & 7;
                CP_ASYNC_16(dst0 + row * ROWV + ch * 16,
                            vsrc[v] + (size_t)row * SS + kt + ch * 8);
            }
        }
        CP_COMMIT();
    };

    const float scale = 0.08838834764831845f;
    float m0 = -INFINITY, m1 = -INFINITY, l0 = 0.f, l1 = 0.f;
    float o[16][4];
#pragma unroll
    for (int dt = 0; dt < 16; dt++)
#pragma unroll
        for (int q = 0; q < 4; q++) o[dt][q] = 0.f;

    const int NIT = SS / AKT;
    load_kv(0);

    for (int it = 0; it < NIT; it++) {
        if (it + 1 < NIT) { load_kv(it + 1); CP_WAIT(1); }
        else              { CP_WAIT(0); }
        __syncthreads();

        const uint32_t smK = smb + (it & 1) * KV_STAGE;
        const uint32_t smV = smK + 2 * KH_BYTES;

        float sc[8][4];
#pragma unroll
        for (int nt = 0; nt < 8; nt++)
#pragma unroll
            for (int q = 0; q < 4; q++) sc[nt][q] = 0.f;

#pragma unroll
        for (int ks = 0; ks < 8; ks++) {
#pragma unroll
            for (int np = 0; np < 4; np++) {
                const uint32_t ro = (np * 16 + lrow) * ROWK + ks * 32 + lcol;
                uint32_t h0, h1, h2, h3, L0, L1, L2, L3;
                ldsm_x4(h0, h1, h2, h3, smK + ro);
                ldsm_x4(L0, L1, L2, L3, smK + KH_BYTES + ro);
                uint32_t b0h[2] = { h0, h2 }, b1h[2] = { h1, h3 };
                uint32_t b0l[2] = { L0, L2 }, b1l[2] = { L1, L3 };
                // interleave the two independent sc tiles, term-major
                mma16816(sc[2*np],   qh[ks], b0h);
                mma16816(sc[2*np+1], qh[ks], b1h);
                mma16816(sc[2*np],   qh[ks], b0l);
                mma16816(sc[2*np+1], qh[ks], b1l);
                mma16816(sc[2*np],   ql[ks], b0h);
                mma16816(sc[2*np+1], ql[ks], b1h);
            }
        }

        float mx0 = -INFINITY, mx1 = -INFINITY;
#pragma unroll
        for (int nt = 0; nt < 8; nt++) {
            mx0 = fmaxf(mx0, fmaxf(sc[nt][0], sc[nt][1]));
            mx1 = fmaxf(mx1, fmaxf(sc[nt][2], sc[nt][3]));
        }
        mx0 = fmaxf(mx0, __shfl_xor_sync(0xffffffffu, mx0, 1));
        mx0 = fmaxf(mx0, __shfl_xor_sync(0xffffffffu, mx0, 2));
        mx1 = fmaxf(mx1, __shfl_xor_sync(0xffffffffu, mx1, 1));
        mx1 = fmaxf(mx1, __shfl_xor_sync(0xffffffffu, mx1, 2));

        const float mn0 = fmaxf(m0, mx0 * scale);
        const float mn1 = fmaxf(m1, mx1 * scale);
        const float a0 = __expf(m0 - mn0);
        const float a1 = __expf(m1 - mn1);
        m0 = mn0; m1 = mn1;

        float rs0 = 0.f, rs1 = 0.f;
        uint32_t ph[8][2], pl[8][2];
#pragma unroll
        for (int nt = 0; nt < 8; nt++) {
            float p0 = __expf(sc[nt][0] * scale - mn0);
            float p1 = __expf(sc[nt][1] * scale - mn0);
            float p2 = __expf(sc[nt][2] * scale - mn1);
            float p3 = __expf(sc[nt][3] * scale - mn1);
            rs0 += p0 + p1; rs1 += p2 + p3;
            ph[nt][0] = pack_split(p0, p1, pl[nt][0]);
            ph[nt][1] = pack_split(p2, p3, pl[nt][1]);
        }
        rs0 += __shfl_xor_sync(0xffffffffu, rs0, 1);
        rs0 += __shfl_xor_sync(0xffffffffu, rs0, 2);
        rs1 += __shfl_xor_sync(0xffffffffu, rs1, 1);
        rs1 += __shfl_xor_sync(0xffffffffu, rs1, 2);
        l0 = l0 * a0 + rs0;
        l1 = l1 * a1 + rs1;

#pragma unroll
        for (int dt = 0; dt < 16; dt++) {
            o[dt][0] *= a0; o[dt][1] *= a0;
            o[dt][2] *= a1; o[dt][3] *= a1;
        }

#pragma unroll
        for (int ks = 0; ks < 4; ks++) {
            uint32_t ah[4] = { ph[2*ks][0], ph[2*ks][1], ph[2*ks+1][0], ph[2*ks+1][1] };
            uint32_t al[4] = { pl[2*ks][0], pl[2*ks][1], pl[2*ks+1][0], pl[2*ks+1][1] };
#pragma unroll
            for (int dp = 0; dp < 8; dp++) {
                const uint32_t ro = (dp * 16 + lrow) * ROWV + ks * 32 + lcol;
                uint32_t h0, h1, h2, h3, L0, L1, L2, L3;
                ldsm_x4(h0, h1, h2, h3, smV + ro);
                ldsm_x4(L0, L1, L2, L3, smV + VH_BYTES + ro);
                uint32_t b0h[2] = { h0, h2 }, b1h[2] = { h1, h3 };
                uint32_t b0l[2] = { L0, L2 }, b1l[2] = { L1, L3 };
                // interleave the two independent o tiles, term-major
                mma16816(o[2*dp],   ah, b0h);
                mma16816(o[2*dp+1], ah, b1h);
                mma16816(o[2*dp],   ah, b0l);
                mma16816(o[2*dp+1], ah, b1l);
                mma16816(o[2*dp],   al, b0h);
                mma16816(o[2*dp+1], al, b1h);
            }
        }
        __syncthreads();
    }

    const float inv0 = 1.0f / l0;
    const float inv1 = 1.0f / l1;
    const int bI = bh >> 4;
    const int h  = bh & 15;
    const int row0 = q0 + wid * 16 + g;
#pragma unroll
    for (int dt = 0; dt < 16; dt++) {
        const int e = h * 128 + dt * 8 + 2 * tig;
        size_t adr0 = (size_t)(bI * SS + row0) * EE + e;
        size_t adr1 = adr0 + (size_t)8 * EE;
        uint32_t lo, hi;
        hi = pack_split(o[dt][0] * inv0, o[dt][1] * inv0, lo);
        *(uint32_t*)&Xh[adr0] = hi; *(uint32_t*)&Xl[adr0] = lo;
        hi = pack_split(o[dt][2] * inv1, o[dt][3] * inv1, lo);
        *(uint32_t*)&Xh[adr1] = hi; *(uint32_t*)&Xl[adr1] = lo;
    }
}

// ---------------------------------------------------------------------------
extern "C" void kernel_launch(void* const* d_in, const int* in_sizes, int n_in,
                              void* d_out, int out_size)
{
    const float* query  = (const float*)d_in[0];
    const float* key_in = (const float*)d_in[1];
    const float* value  = (const float*)d_in[2];
    const float* Wq = (const float*)d_in[3];
    const float* bq = (const float*)d_in[4];
    const float* Wk = (const float*)d_in[5];
    const float* bk = (const float*)d_in[6];
    const float* Wv = (const float*)d_in[7];
    const float* bv = (const float*)d_in[8];
    const float* Wo = (const float*)d_in[9];
    const float* bo = (const float*)d_in[10];
    float* out = (float*)d_out;

    __nv_bfloat16 *Qh, *Ql, *Kh, *Kl, *Vh, *Vl;
    __nv_bfloat16 *X1h, *X1l, *X2h, *X2l, *X3h, *X3l, *Wth, *Wtl;
    cudaGetSymbolAddress((void**)&Qh, g_Qh);
    cudaGetSymbolAddress((void**)&Ql, g_Ql);
    cudaGetSymbolAddress((void**)&Kh, g_Kh);
    cudaGetSymbolAddress((void**)&Kl, g_Kl);
    cudaGetSymbolAddress((void**)&Vh, g_Vh);
    cudaGetSymbolAddress((void**)&Vl, g_Vl);
    cudaGetSymbolAddress((void**)&X1h, g_X1h);
    cudaGetSymbolAddress((void**)&X1l, g_X1l);
    cudaGetSymbolAddress((void**)&X2h, g_X2h);
    cudaGetSymbolAddress((void**)&X2l, g_X2l);
    cudaGetSymbolAddress((void**)&X3h, g_X3h);
    cudaGetSymbolAddress((void**)&X3l, g_X3l);
    cudaGetSymbolAddress((void**)&Wth, g_Wth);
    cudaGetSymbolAddress((void**)&Wtl, g_Wtl);

    cudaFuncSetAttribute(gemm_mma_kernel<0>, cudaFuncAttributeMaxDynamicSharedMemorySize, GEMM_SMEM);
    cudaFuncSetAttribute(gemm_mma_kernel<1>, cudaFuncAttributeMaxDynamicSharedMemorySize, GEMM_SMEM);
    cudaFuncSetAttribute(gemm_mma_kernel<2>, cudaFuncAttributeMaxDynamicSharedMemorySize, GEMM_SMEM);
    cudaFuncSetAttribute(attn_mma_kernel, cudaFuncAttributeMaxDynamicSharedMemorySize, ATTN_SMEM);

    const int n4 = MROWS * EE / 4;
    const size_t WSZ = (size_t)EE * EE;
    dim3 gt(EE/32, EE/32, 4), bt(32, 32);
    dim3 gg(EE/BN, MROWS/BM);          // (8, 32) = 256 blocks
    dim3 gs(1024, 3);

    split3_kernel<<<gs, 256>>>(query, key_in, value, X1h, X1l, X2h, X2l, X3h, X3l, n4);
    transpose4_kernel<<<gt, bt>>>(Wq, Wk, Wv, Wo, Wth, Wtl);

    gemm_mma_kernel<1><<<gg, 256, GEMM_SMEM>>>(X1h, X1l, Wth + 0*WSZ, Wtl + 0*WSZ, bq, nullptr, Qh, Ql);
    gemm_mma_kernel<1><<<gg, 256, GEMM_SMEM>>>(X2h, X2l, Wth + 1*WSZ, Wtl + 1*WSZ, bk, nullptr, Kh, Kl);
    gemm_mma_kernel<2><<<gg, 256, GEMM_SMEM>>>(X3h, X3l, Wth + 2*WSZ, Wtl + 2*WSZ, bv, nullptr, Vh, Vl);

    dim3 ga(SS/AQT, BB*HH);            // (16, 32)
    attn_mma_kernel<<<ga, 256, ATTN_SMEM>>>(Qh, Ql, Kh, Kl, Vh, Vl, X1h, X1l);

    gemm_mma_kernel<0><<<gg, 256, GEMM_SMEM>>>(X1h, X1l, Wth + 3*WSZ, Wtl + 3*WSZ, bo, out, nullptr, nullptr);
}

// round 12
// speedup vs baseline: 2.1966x; 2.1966x over previous
#include <cuda_runtime.h>
#include <cuda_fp16.h>
#include <cstdint>
#include <math.h>

#define BB 2
#define SS 2048
#define EE 2048
#define HH 16
#define DD 128
#define MROWS (BB*SS)   // 4096

// ---------------- device scratch (fp16) ----------------
__device__ __half g_Qh[MROWS*EE];  // [B*H, S, D] hi
__device__ __half g_Ql[MROWS*EE];  // lo
__device__ __half g_Kh[MROWS*EE];  // [B*H, S, D] single
__device__ __half g_Vh[MROWS*EE];  // [B*H, D, S] single (transposed)
__device__ __half g_X1h[MROWS*EE];
__device__ __half g_X1l[MROWS*EE];
__device__ __half g_X2h[MROWS*EE];
__device__ __half g_X2l[MROWS*EE];
__device__ __half g_X3h[MROWS*EE];
__device__ __half g_X3l[MROWS*EE];
__device__ __half g_Wth[4*EE*EE];  // 4 weights, W^T single fp16 [n][k]

// ---------------- primitives ----------------
__device__ __forceinline__ uint32_t smem_u32(const void* p) {
    uint32_t a;
    asm("{ .reg .u64 t; cvta.to.shared.u64 t, %1; cvt.u32.u64 %0, t; }" : "=r"(a) : "l"(p));
    return a;
}
#define CP_ASYNC_16(dst_u32, src_ptr) \
    asm volatile("cp.async.cg.shared.global [%0], [%1], 16;" :: "r"(dst_u32), "l"(src_ptr))
#define CP_COMMIT() asm volatile("cp.async.commit_group;" ::: "memory")
#define CP_WAIT(n)  asm volatile("cp.async.wait_group %0;" :: "n"(n) : "memory")

__device__ __forceinline__ void mma16816(float* c, const uint32_t* a, const uint32_t* b) {
    asm volatile(
        "mma.sync.aligned.m16n8k16.row.col.f32.f16.f16.f32 "
        "{%0,%1,%2,%3}, {%4,%5,%6,%7}, {%8,%9}, {%0,%1,%2,%3};"
        : "+f"(c[0]), "+f"(c[1]), "+f"(c[2]), "+f"(c[3])
        : "r"(a[0]), "r"(a[1]), "r"(a[2]), "r"(a[3]), "r"(b[0]), "r"(b[1]));
}

__device__ __forceinline__ void ldsm_x4(uint32_t& r0, uint32_t& r1, uint32_t& r2,
                                        uint32_t& r3, uint32_t addr) {
    asm volatile("ldmatrix.sync.aligned.m8n8.x4.shared.b16 {%0,%1,%2,%3}, [%4];"
                 : "=r"(r0), "=r"(r1), "=r"(r2), "=r"(r3) : "r"(addr));
}

// pack two floats: hi = fp16x2 round, lo = fp16x2 residual
__device__ __forceinline__ uint32_t pack_split_h(float x, float y, uint32_t& lo) {
    __half hx = __float2half_rn(x), hy = __float2half_rn(y);
    __half lx = __float2half_rn(x - __half2float(hx));
    __half ly = __float2half_rn(y - __half2float(hy));
    __half2 hp; hp.x = hx; hp.y = hy;
    __half2 lp; lp.x = lx; lp.y = ly;
    lo = *(uint32_t*)&lp;
    return *(uint32_t*)&hp;
}

// ---------------------------------------------------------------------------
// Conversion kernels
// ---------------------------------------------------------------------------
__global__ __launch_bounds__(256)
void split3_kernel(const float* __restrict__ X0, const float* __restrict__ X1,
                   const float* __restrict__ X2,
                   __half* __restrict__ H0, __half* __restrict__ L0,
                   __half* __restrict__ H1, __half* __restrict__ L1,
                   __half* __restrict__ H2, __half* __restrict__ L2,
                   int n4)
{
    const int z = blockIdx.y;
    const float* X = (z == 0) ? X0 : (z == 1) ? X1 : X2;
    __half* H = (z == 0) ? H0 : (z == 1) ? H1 : H2;
    __half* L = (z == 0) ? L0 : (z == 1) ? L1 : L2;
    int i = blockIdx.x * blockDim.x + threadIdx.x;
    const int stride = gridDim.x * blockDim.x;
    for (; i < n4; i += stride) {
        float4 v = ((const float4*)X)[i];
        uint32_t l0, l1;
        uint32_t h0 = pack_split_h(v.x, v.y, l0);
        uint32_t h1 = pack_split_h(v.z, v.w, l1);
        ((uint32_t*)H)[2*i]   = h0;
        ((uint32_t*)H)[2*i+1] = h1;
        ((uint32_t*)L)[2*i]   = l0;
        ((uint32_t*)L)[2*i+1] = l1;
    }
}

// W [k][n] fp32 -> W^T single fp16 [n][k]
__global__ __launch_bounds__(1024)
void transpose4_kernel(const float* __restrict__ W0, const float* __restrict__ W1,
                       const float* __restrict__ W2, const float* __restrict__ W3,
                       __half* __restrict__ Th)
{
    __shared__ float t[32][33];
    const int z = blockIdx.z;
    const float* W = (z == 0) ? W0 : (z == 1) ? W1 : (z == 2) ? W2 : W3;
    __half* TH = Th + (size_t)z * EE * EE;
    const int n0 = blockIdx.x * 32, k0 = blockIdx.y * 32;
    const int tx = threadIdx.x, ty = threadIdx.y;
    t[ty][tx] = W[(size_t)(k0 + ty) * EE + n0 + tx];
    __syncthreads();
    TH[(size_t)(n0 + ty) * EE + k0 + tx] = __float2half_rn(t[tx][ty]);
}

// ---------------------------------------------------------------------------
// 2-term fp16 mma.sync GEMM (A split hi/lo, B single), ldmatrix loads.
// R8 geometry: BM=128, BN=256, BK=32, 2-stage, 8 warps (2x4), warp 64x64.
// MODE 0: fp32 [m][n]. MODE 1: split fp16 head-major [B*H,S,D].
// MODE 2: single fp16 head-major TRANSPOSED [B*H,D,S]. MODE 3: single fp16 head-major.
// ---------------------------------------------------------------------------
#define BM 128
#define BN 256
#define BK 32
#define ROWB 112                       // 64B data + 48B pad (conflict-free LDSM)
#define A_BYTES (BM*ROWB)              // 14336
#define B_BYTES (BN*ROWB)              // 28672
#define STAGE_BYTES (2*A_BYTES + B_BYTES)   // 57344 (Ah, Al, Bh)
#define GEMM_SMEM (2*STAGE_BYTES)           // 114688

template<int MODE>
__global__ __launch_bounds__(256)
void gemm_mma_kernel(const __half* __restrict__ Xh, const __half* __restrict__ Xl,
                     const __half* __restrict__ Wh,
                     const float* __restrict__ bias, float* __restrict__ Yf,
                     __half* __restrict__ Yh, __half* __restrict__ Yl)
{
    extern __shared__ char sm[];
    const int tid  = threadIdx.x;
    const int lane = tid & 31;
    const int wid  = tid >> 5;
    const int g    = lane >> 2;
    const int tig  = lane & 3;

    const int m0 = blockIdx.y * BM;
    const int n0 = blockIdx.x * BN;
    const int wm = (wid & 1) * 64;
    const int wn = (wid >> 1) * 64;

    const uint32_t smb = smem_u32(sm);
    const uint32_t lrow = (lane & 15);
    const uint32_t lcol = (lane >> 4) * 16;

    float c[4][8][4];
#pragma unroll
    for (int i = 0; i < 4; i++)
#pragma unroll
        for (int j = 0; j < 8; j++)
#pragma unroll
            for (int q = 0; q < 4; q++) c[i][j][q] = 0.f;

    const __half* srcA[2] = { Xh + (size_t)m0*EE, Xl + (size_t)m0*EE };
    const __half* srcB = Wh + (size_t)n0*EE;

    auto load_stage = [&](int s) {
        const int buf = s & 1;
        const uint32_t base = smb + buf * STAGE_BYTES;
        const int k0 = s * BK;
#pragma unroll
        for (int v = 0; v < 2; v++) {
            const __half* src = srcA[v] + k0;
            const uint32_t dst0 = base + v * A_BYTES;
#pragma unroll
            for (int i = 0; i < 2; i++) {
                int idx = tid + i * 256;           // 0..511
                int r = idx >> 2, ch = idx & 3;
                CP_ASYNC_16(dst0 + r * ROWB + ch * 16, src + (size_t)r * EE + ch * 8);
            }
        }
        {
            const __half* src = srcB + k0;
            const uint32_t dst0 = base + 2 * A_BYTES;
#pragma unroll
            for (int i = 0; i < 4; i++) {
                int idx = tid + i * 256;           // 0..1023
                int r = idx >> 2, ch = idx & 3;
                CP_ASYNC_16(dst0 + r * ROWB + ch * 16, src + (size_t)r * EE + ch * 8);
            }
        }
        CP_COMMIT();
    };

    const int NS = EE / BK;   // 64
    load_stage(0);

    for (int s = 0; s < NS; s++) {
        const int buf = s & 1;
        if (s + 1 < NS) { load_stage(s + 1); CP_WAIT(1); }
        else            { CP_WAIT(0); }
        __syncthreads();

        const uint32_t Ah = smb + buf * STAGE_BYTES;
        const uint32_t Al = Ah + A_BYTES;
        const uint32_t Bh = Ah + 2 * A_BYTES;

#pragma unroll
        for (int kb = 0; kb < BK; kb += 16) {
            const uint32_t kbyte = kb * 2 + lcol;
            uint32_t ah[4][4], al[4][4], bh[8][2];
#pragma unroll
            for (int mt = 0; mt < 4; mt++) {
                const uint32_t ro = (wm + mt * 16 + lrow) * ROWB + kbyte;
                ldsm_x4(ah[mt][0], ah[mt][1], ah[mt][2], ah[mt][3], Ah + ro);
                ldsm_x4(al[mt][0], al[mt][1], al[mt][2], al[mt][3], Al + ro);
            }
#pragma unroll
            for (int np = 0; np < 4; np++) {
                const uint32_t ro = (wn + np * 16 + lrow) * ROWB + kbyte;
                uint32_t h0, h1, h2, h3;
                ldsm_x4(h0, h1, h2, h3, Bh + ro);
                bh[2*np][0] = h0; bh[2*np][1] = h2;
                bh[2*np+1][0] = h1; bh[2*np+1][1] = h3;
            }
#pragma unroll
            for (int mt = 0; mt < 4; mt++)
#pragma unroll
                for (int nt = 0; nt < 8; nt++) {
                    mma16816(c[mt][nt], ah[mt], bh[nt]);
                    mma16816(c[mt][nt], al[mt], bh[nt]);
                }
        }
        __syncthreads();
    }

    // ---- epilogue ----
#pragma unroll
    for (int mt = 0; mt < 4; mt++) {
        const int m = m0 + wm + mt * 16 + g;
        const int bI = m >> 11;
        const int sI = m & (SS - 1);
#pragma unroll
        for (int nt = 0; nt < 8; nt++) {
            const int n = n0 + wn + nt * 8 + 2 * tig;
            const float b0 = bias[n], b1 = bias[n + 1];
            const float y0 = c[mt][nt][0] + b0, y1 = c[mt][nt][1] + b1;
            const float y2 = c[mt][nt][2] + b0, y3 = c[mt][nt][3] + b1;
            if (MODE == 0) {
                size_t o0 = (size_t)m * EE + n;
                float2 v0; v0.x = y0; v0.y = y1;
                float2 v1; v1.x = y2; v1.y = y3;
                *(float2*)&Yf[o0] = v0;
                *(float2*)&Yf[o0 + 8 * EE] = v1;
            } else if (MODE == 1) {
                const int h = n >> 7, d = n & 127;
                size_t o0 = (((size_t)(bI * HH + h) * SS + sI) * DD) + d;
                uint32_t lo, hi;
                hi = pack_split_h(y0, y1, lo);
                *(uint32_t*)&Yh[o0] = hi; *(uint32_t*)&Yl[o0] = lo;
                hi = pack_split_h(y2, y3, lo);
                *(uint32_t*)&Yh[o0 + 8 * DD] = hi; *(uint32_t*)&Yl[o0 + 8 * DD] = lo;
            } else if (MODE == 3) {
                const int h = n >> 7, d = n & 127;
                size_t o0 = (((size_t)(bI * HH + h) * SS + sI) * DD) + d;
                __half2 p0; p0.x = __float2half_rn(y0); p0.y = __float2half_rn(y1);
                __half2 p1; p1.x = __float2half_rn(y2); p1.y = __float2half_rn(y3);
                *(__half2*)&Yh[o0] = p0;
                *(__half2*)&Yh[o0 + 8 * DD] = p1;
            } else {
                const int h = n >> 7, d = n & 127;
                const size_t base = (size_t)(bI * HH + h) * DD;
                size_t o00 = (base + d) * SS + sI;
                size_t o01 = (base + d + 1) * SS + sI;
                Yh[o00]     = __float2half_rn(y0);
                Yh[o01]     = __float2half_rn(y1);
                Yh[o00 + 8] = __float2half_rn(y2);
                Yh[o01 + 8] = __float2half_rn(y3);
            }
        }
    }
}

// ---------------------------------------------------------------------------
// Flash attention: Q split fp16 (2-term), K/V single fp16, ldmatrix,
// double-buffered K/V cp.async.
// ---------------------------------------------------------------------------
#define AQT 128
#define AKT 64
#define ROWK 272
#define ROWV 144
#define KH_BYTES (64*ROWK)          // 17408
#define VH_BYTES (128*ROWV)         // 18432
#define KV_STAGE (KH_BYTES + VH_BYTES)   // 35840
#define ATTN_SMEM (2*KV_STAGE)           // 71680 (>= Q phase 69632)

__global__ __launch_bounds__(256)
void attn_mma_kernel(const __half* __restrict__ Qh_, const __half* __restrict__ Ql_,
                     const __half* __restrict__ Kh_, const __half* __restrict__ Vh_,
                     __half* __restrict__ Xh, __half* __restrict__ Xl)
{
    extern __shared__ char sm[];
    const uint32_t smb = smem_u32(sm);
    const int tid  = threadIdx.x;
    const int lane = tid & 31;
    const int wid  = tid >> 5;
    const int g    = lane >> 2;
    const int tig  = lane & 3;
    const uint32_t lrow = (lane & 15);
    const uint32_t lcol = (lane >> 4) * 16;

    const int bh = blockIdx.y;
    const int q0 = blockIdx.x * AQT;
    const size_t hoff = (size_t)bh * SS * DD;

    const __half* ksrc = Kh_ + hoff;
    const __half* vsrc = Vh_ + (size_t)bh * DD * SS;

    // ---- Q tile (128x128 hi/lo) to smem, then fragments via ldmatrix ----
    {
        const __half* qsrc[2] = { Qh_ + hoff + (size_t)q0 * DD,
                                  Ql_ + hoff + (size_t)q0 * DD };
#pragma unroll
        for (int v = 0; v < 2; v++) {
            const uint32_t dst0 = smb + v * (128 * ROWK);
#pragma unroll
            for (int i = 0; i < 8; i++) {
                int idx = tid + i * 256;
                int row = idx >> 4, ch = idx & 15;
                CP_ASYNC_16(dst0 + row * ROWK + ch * 16, qsrc[v] + (size_t)row * DD + ch * 8);
            }
        }
        CP_COMMIT(); CP_WAIT(0);
        __syncthreads();
    }

    uint32_t qh[8][4], ql[8][4];
    {
        const uint32_t ro = (wid * 16 + lrow) * ROWK + lcol;
#pragma unroll
        for (int ks = 0; ks < 8; ks++) {
            ldsm_x4(qh[ks][0], qh[ks][1], qh[ks][2], qh[ks][3], smb + ro + ks * 32);
            ldsm_x4(ql[ks][0], ql[ks][1], ql[ks][2], ql[ks][3],
                    smb + 128 * ROWK + ro + ks * 32);
        }
    }
    __syncthreads();

    auto load_kv = [&](int it) {
        const uint32_t base = smb + (it & 1) * KV_STAGE;
        const int kt = it * AKT;
        {   // K hi: 64 rows x 16 chunks = 1024
#pragma unroll
            for (int i = 0; i < 4; i++) {
                int idx = tid + i * 256;
                int row = idx >> 4, ch = idx & 15;
                CP_ASYNC_16(base + row * ROWK + ch * 16,
                            ksrc + (size_t)(kt + row) * DD + ch * 8);
            }
        }
        {   // V hi: 128 rows x 8 chunks = 1024
            const uint32_t dst0 = base + KH_BYTES;
#pragma unroll
            for (int i = 0; i < 4; i++) {
                int idx = tid + i * 256;
                int row = idx >> 3, ch = idx & 7;
                CP_ASYNC_16(dst0 + row * ROWV + ch * 16,
                            vsrc + (size_t)row * SS + kt + ch * 8);
            }
        }
        CP_COMMIT();
    };

    const float scale = 0.08838834764831845f;
    float m0 = -INFINITY, m1 = -INFINITY, l0 = 0.f, l1 = 0.f;
    float o[16][4];
#pragma unroll
    for (int dt = 0; dt < 16; dt++)
#pragma unroll
        for (int q = 0; q < 4; q++) o[dt][q] = 0.f;

    const int NIT = SS / AKT;
    load_kv(0);

    for (int it = 0; it < NIT; it++) {
        if (it + 1 < NIT) { load_kv(it + 1); CP_WAIT(1); }
        else              { CP_WAIT(0); }
        __syncthreads();

        const uint32_t smK = smb + (it & 1) * KV_STAGE;
        const uint32_t smV = smK + KH_BYTES;

        // ---- scores: 2-term (Qh + Ql) x K ----
        float sc[8][4];
#pragma unroll
        for (int nt = 0; nt < 8; nt++)
#pragma unroll
            for (int q = 0; q < 4; q++) sc[nt][q] = 0.f;

#pragma unroll
        for (int ks = 0; ks < 8; ks++) {
#pragma unroll
            for (int np = 0; np < 4; np++) {
                const uint32_t ro = (np * 16 + lrow) * ROWK + ks * 32 + lcol;
                uint32_t h0, h1, h2, h3;
                ldsm_x4(h0, h1, h2, h3, smK + ro);
                uint32_t b0h[2] = { h0, h2 }, b1h[2] = { h1, h3 };
                mma16816(sc[2*np],   qh[ks], b0h);
                mma16816(sc[2*np],   ql[ks], b0h);
                mma16816(sc[2*np+1], qh[ks], b1h);
                mma16816(sc[2*np+1], ql[ks], b1h);
            }
        }

        // ---- online softmax ----
        float mx0 = -INFINITY, mx1 = -INFINITY;
#pragma unroll
        for (int nt = 0; nt < 8; nt++) {
            mx0 = fmaxf(mx0, fmaxf(sc[nt][0], sc[nt][1]));
            mx1 = fmaxf(mx1, fmaxf(sc[nt][2], sc[nt][3]));
        }
        mx0 = fmaxf(mx0, __shfl_xor_sync(0xffffffffu, mx0, 1));
        mx0 = fmaxf(mx0, __shfl_xor_sync(0xffffffffu, mx0, 2));
        mx1 = fmaxf(mx1, __shfl_xor_sync(0xffffffffu, mx1, 1));
        mx1 = fmaxf(mx1, __shfl_xor_sync(0xffffffffu, mx1, 2));

        const float mn0 = fmaxf(m0, mx0 * scale);
        const float mn1 = fmaxf(m1, mx1 * scale);
        const float a0 = __expf(m0 - mn0);
        const float a1 = __expf(m1 - mn1);
        m0 = mn0; m1 = mn1;

        float rs0 = 0.f, rs1 = 0.f;
        uint32_t ph[8][2], pl[8][2];
#pragma unroll
        for (int nt = 0; nt < 8; nt++) {
            float p0 = __expf(sc[nt][0] * scale - mn0);
            float p1 = __expf(sc[nt][1] * scale - mn0);
            float p2 = __expf(sc[nt][2] * scale - mn1);
            float p3 = __expf(sc[nt][3] * scale - mn1);
            rs0 += p0 + p1; rs1 += p2 + p3;
            ph[nt][0] = pack_split_h(p0, p1, pl[nt][0]);
            ph[nt][1] = pack_split_h(p2, p3, pl[nt][1]);
        }
        rs0 += __shfl_xor_sync(0xffffffffu, rs0, 1);
        rs0 += __shfl_xor_sync(0xffffffffu, rs0, 2);
        rs1 += __shfl_xor_sync(0xffffffffu, rs1, 1);
        rs1 += __shfl_xor_sync(0xffffffffu, rs1, 2);
        l0 = l0 * a0 + rs0;
        l1 = l1 * a1 + rs1;

#pragma unroll
        for (int dt = 0; dt < 16; dt++) {
            o[dt][0] *= a0; o[dt][1] *= a0;
            o[dt][2] *= a1; o[dt][3] *= a1;
        }

        // ---- PV: 2-term (Ph + Pl) x V ----
#pragma unroll
        for (int ks = 0; ks < 4; ks++) {
            uint32_t ah[4] = { ph[2*ks][0], ph[2*ks][1], ph[2*ks+1][0], ph[2*ks+1][1] };
            uint32_t al[4] = { pl[2*ks][0], pl[2*ks][1], pl[2*ks+1][0], pl[2*ks+1][1] };
#pragma unroll
            for (int dp = 0; dp < 8; dp++) {
                const uint32_t ro = (dp * 16 + lrow) * ROWV + ks * 32 + lcol;
                uint32_t h0, h1, h2, h3;
                ldsm_x4(h0, h1, h2, h3, smV + ro);
                uint32_t b0h[2] = { h0, h2 }, b1h[2] = { h1, h3 };
                mma16816(o[2*dp],   ah, b0h);
                mma16816(o[2*dp],   al, b0h);
                mma16816(o[2*dp+1], ah, b1h);
                mma16816(o[2*dp+1], al, b1h);
            }
        }
        __syncthreads();
    }

    // ---- epilogue: normalize, split fp16, store ----
    const float inv0 = 1.0f / l0;
    const float inv1 = 1.0f / l1;
    const int bI = bh >> 4;
    const int h  = bh & 15;
    const int row0 = q0 + wid * 16 + g;
#pragma unroll
    for (int dt = 0; dt < 16; dt++) {
        const int e = h * 128 + dt * 8 + 2 * tig;
        size_t adr0 = (size_t)(bI * SS + row0) * EE + e;
        size_t adr1 = adr0 + (size_t)8 * EE;
        uint32_t lo, hi;
        hi = pack_split_h(o[dt][0] * inv0, o[dt][1] * inv0, lo);
        *(uint32_t*)&Xh[adr0] = hi; *(uint32_t*)&Xl[adr0] = lo;
        hi = pack_split_h(o[dt][2] * inv1, o[dt][3] * inv1, lo);
        *(uint32_t*)&Xh[adr1] = hi; *(uint32_t*)&Xl[adr1] = lo;
    }
}

// ---------------------------------------------------------------------------
extern "C" void kernel_launch(void* const* d_in, const int* in_sizes, int n_in,
                              void* d_out, int out_size)
{
    const float* query  = (const float*)d_in[0];
    const float* key_in = (const float*)d_in[1];
    const float* value  = (const float*)d_in[2];
    const float* Wq = (const float*)d_in[3];
    const float* bq = (const float*)d_in[4];
    const float* Wk = (const float*)d_in[5];
    const float* bk = (const float*)d_in[6];
    const float* Wv = (const float*)d_in[7];
    const float* bv = (const float*)d_in[8];
    const float* Wo = (const float*)d_in[9];
    const float* bo = (const float*)d_in[10];
    float* out = (float*)d_out;

    __half *Qh, *Ql, *Kh, *Vh;
    __half *X1h, *X1l, *X2h, *X2l, *X3h, *X3l, *Wth;
    cudaGetSymbolAddress((void**)&Qh, g_Qh);
    cudaGetSymbolAddress((void**)&Ql, g_Ql);
    cudaGetSymbolAddress((void**)&Kh, g_Kh);
    cudaGetSymbolAddress((void**)&Vh, g_Vh);
    cudaGetSymbolAddress((void**)&X1h, g_X1h);
    cudaGetSymbolAddress((void**)&X1l, g_X1l);
    cudaGetSymbolAddress((void**)&X2h, g_X2h);
    cudaGetSymbolAddress((void**)&X2l, g_X2l);
    cudaGetSymbolAddress((void**)&X3h, g_X3h);
    cudaGetSymbolAddress((void**)&X3l, g_X3l);
    cudaGetSymbolAddress((void**)&Wth, g_Wth);

    cudaFuncSetAttribute(gemm_mma_kernel<0>, cudaFuncAttributeMaxDynamicSharedMemorySize, GEMM_SMEM);
    cudaFuncSetAttribute(gemm_mma_kernel<1>, cudaFuncAttributeMaxDynamicSharedMemorySize, GEMM_SMEM);
    cudaFuncSetAttribute(gemm_mma_kernel<2>, cudaFuncAttributeMaxDynamicSharedMemorySize, GEMM_SMEM);
    cudaFuncSetAttribute(gemm_mma_kernel<3>, cudaFuncAttributeMaxDynamicSharedMemorySize, GEMM_SMEM);
    cudaFuncSetAttribute(attn_mma_kernel, cudaFuncAttributeMaxDynamicSharedMemorySize, ATTN_SMEM);

    const int n4 = MROWS * EE / 4;
    const size_t WSZ = (size_t)EE * EE;
    dim3 gt(EE/32, EE/32, 4), bt(32, 32);
    dim3 gg(EE/BN, MROWS/BM);          // (8, 32) = 256 blocks
    dim3 gs(1024, 3);

    split3_kernel<<<gs, 256>>>(query, key_in, value, X1h, X1l, X2h, X2l, X3h, X3l, n4);
    transpose4_kernel<<<gt, bt>>>(Wq, Wk, Wv, Wo, Wth);

    gemm_mma_kernel<1><<<gg, 256, GEMM_SMEM>>>(X1h, X1l, Wth + 0*WSZ, bq, nullptr, Qh, Ql);
    gemm_mma_kernel<3><<<gg, 256, GEMM_SMEM>>>(X2h, X2l, Wth + 1*WSZ, bk, nullptr, Kh, nullptr);
    gemm_mma_kernel<2><<<gg, 256, GEMM_SMEM>>>(X3h, X3l, Wth + 2*WSZ, bv, nullptr, Vh, nullptr);

    dim3 ga(SS/AQT, BB*HH);            // (16, 32)
    attn_mma_kernel<<<ga, 256, ATTN_SMEM>>>(Qh, Ql, Kh, Vh, X1h, X1l);

    gemm_mma_kernel<0><<<gg, 256, GEMM_SMEM>>>(X1h, X1l, Wth + 3*WSZ, bo, out, nullptr, nullptr);
}

// round 13
// speedup vs baseline: 2.4876x; 1.1325x over previous
#include <cuda_runtime.h>
#include <cuda_fp16.h>
#include <cstdint>
#include <math.h>

#define BB 2
#define SS 2048
#define EE 2048
#define HH 16
#define DD 128
#define MROWS (BB*SS)   // 4096

// ---------------- device scratch (fp16) ----------------
__device__ __half g_Qh[MROWS*EE];  // [B*H, S, D] hi
__device__ __half g_Ql[MROWS*EE];  // lo
__device__ __half g_Kh[MROWS*EE];  // [B*H, S, D] single
__device__ __half g_Vh[MROWS*EE];  // [B*H, D, S] single (transposed)
__device__ __half g_X1h[MROWS*EE];
__device__ __half g_X1l[MROWS*EE];
__device__ __half g_X2h[MROWS*EE];
__device__ __half g_X3h[MROWS*EE];
__device__ __half g_Wth[4*EE*EE];  // 4 weights, W^T single fp16 [n][k]

// ---------------- primitives ----------------
__device__ __forceinline__ uint32_t smem_u32(const void* p) {
    uint32_t a;
    asm("{ .reg .u64 t; cvta.to.shared.u64 t, %1; cvt.u32.u64 %0, t; }" : "=r"(a) : "l"(p));
    return a;
}
#define CP_ASYNC_16(dst_u32, src_ptr) \
    asm volatile("cp.async.cg.shared.global [%0], [%1], 16;" :: "r"(dst_u32), "l"(src_ptr))
#define CP_COMMIT() asm volatile("cp.async.commit_group;" ::: "memory")
#define CP_WAIT(n)  asm volatile("cp.async.wait_group %0;" :: "n"(n) : "memory")

__device__ __forceinline__ void mma16816(float* c, const uint32_t* a, const uint32_t* b) {
    asm volatile(
        "mma.sync.aligned.m16n8k16.row.col.f32.f16.f16.f32 "
        "{%0,%1,%2,%3}, {%4,%5,%6,%7}, {%8,%9}, {%0,%1,%2,%3};"
        : "+f"(c[0]), "+f"(c[1]), "+f"(c[2]), "+f"(c[3])
        : "r"(a[0]), "r"(a[1]), "r"(a[2]), "r"(a[3]), "r"(b[0]), "r"(b[1]));
}

__device__ __forceinline__ void ldsm_x4(uint32_t& r0, uint32_t& r1, uint32_t& r2,
                                        uint32_t& r3, uint32_t addr) {
    asm volatile("ldmatrix.sync.aligned.m8n8.x4.shared.b16 {%0,%1,%2,%3}, [%4];"
                 : "=r"(r0), "=r"(r1), "=r"(r2), "=r"(r3) : "r"(addr));
}

__device__ __forceinline__ uint32_t pack_split_h(float x, float y, uint32_t& lo) {
    __half hx = __float2half_rn(x), hy = __float2half_rn(y);
    __half lx = __float2half_rn(x - __half2float(hx));
    __half ly = __float2half_rn(y - __half2float(hy));
    __half2 hp; hp.x = hx; hp.y = hy;
    __half2 lp; lp.x = lx; lp.y = ly;
    lo = *(uint32_t*)&lp;
    return *(uint32_t*)&hp;
}
__device__ __forceinline__ uint32_t pack2_h(float x, float y) {
    __half2 p; p.x = __float2half_rn(x); p.y = __float2half_rn(y);
    return *(uint32_t*)&p;
}

// ---------------------------------------------------------------------------
// Conversion kernels
// ---------------------------------------------------------------------------
// z=0: query -> H0 + L0 (split). z=1: key -> H1 single. z=2: value -> H2 single.
__global__ __launch_bounds__(256)
void split3_kernel(const float* __restrict__ X0, const float* __restrict__ X1,
                   const float* __restrict__ X2,
                   __half* __restrict__ H0, __half* __restrict__ L0,
                   __half* __restrict__ H1, __half* __restrict__ H2,
                   int n4)
{
    const int z = blockIdx.y;
    const float* X = (z == 0) ? X0 : (z == 1) ? X1 : X2;
    __half* H = (z == 0) ? H0 : (z == 1) ? H1 : H2;
    int i = blockIdx.x * blockDim.x + threadIdx.x;
    const int stride = gridDim.x * blockDim.x;
    for (; i < n4; i += stride) {
        float4 v = ((const float4*)X)[i];
        if (z == 0) {
            uint32_t l0, l1;
            uint32_t h0 = pack_split_h(v.x, v.y, l0);
            uint32_t h1 = pack_split_h(v.z, v.w, l1);
            ((uint32_t*)H)[2*i]   = h0;
            ((uint32_t*)H)[2*i+1] = h1;
            ((uint32_t*)L0)[2*i]   = l0;
            ((uint32_t*)L0)[2*i+1] = l1;
        } else {
            ((uint32_t*)H)[2*i]   = pack2_h(v.x, v.y);
            ((uint32_t*)H)[2*i+1] = pack2_h(v.z, v.w);
        }
    }
}

__global__ __launch_bounds__(1024)
void transpose4_kernel(const float* __restrict__ W0, const float* __restrict__ W1,
                       const float* __restrict__ W2, const float* __restrict__ W3,
                       __half* __restrict__ Th)
{
    __shared__ float t[32][33];
    const int z = blockIdx.z;
    const float* W = (z == 0) ? W0 : (z == 1) ? W1 : (z == 2) ? W2 : W3;
    __half* TH = Th + (size_t)z * EE * EE;
    const int n0 = blockIdx.x * 32, k0 = blockIdx.y * 32;
    const int tx = threadIdx.x, ty = threadIdx.y;
    t[ty][tx] = W[(size_t)(k0 + ty) * EE + n0 + tx];
    __syncthreads();
    TH[(size_t)(n0 + ty) * EE + k0 + tx] = __float2half_rn(t[tx][ty]);
}

// ---------------------------------------------------------------------------
// Shared GEMM geometry
// ---------------------------------------------------------------------------
#define BM 128
#define BN 256
#define BK 32
#define ROWB 112
#define A_BYTES (BM*ROWB)              // 14336
#define B_BYTES (BN*ROWB)              // 28672
#define STAGE_BYTES (2*A_BYTES + B_BYTES)   // 57344 (Ah, Al, B)
#define GEMM_SMEM (2*STAGE_BYTES)           // 114688

// ---------------------------------------------------------------------------
// Batched QKV projection GEMM. blockIdx.z: 0=Q (2-term A, split out),
// 1=K (1-term, single out head-major), 2=V (1-term, single out transposed).
// ---------------------------------------------------------------------------
__global__ __launch_bounds__(256)
void qkv_gemm_kernel(const __half* __restrict__ X1h, const __half* __restrict__ X1l,
                     const __half* __restrict__ X2h, const __half* __restrict__ X3h,
                     const __half* __restrict__ Wt,
                     const float* __restrict__ bq, const float* __restrict__ bk,
                     const float* __restrict__ bv,
                     __half* __restrict__ Qh, __half* __restrict__ Ql,
                     __half* __restrict__ Kh, __half* __restrict__ Vh)
{
    extern __shared__ char sm[];
    const int z = blockIdx.z;
    const bool twoTerm = (z == 0);
    const __half* Xh = (z == 0) ? X1h : (z == 1) ? X2h : X3h;
    const __half* Wh = Wt + (size_t)z * EE * EE;
    const float* bias = (z == 0) ? bq : (z == 1) ? bk : bv;

    const int tid  = threadIdx.x;
    const int lane = tid & 31;
    const int wid  = tid >> 5;
    const int g    = lane >> 2;
    const int tig  = lane & 3;

    const int m0 = blockIdx.y * BM;
    const int n0 = blockIdx.x * BN;
    const int wm = (wid & 1) * 64;
    const int wn = (wid >> 1) * 64;

    const uint32_t smb = smem_u32(sm);
    const uint32_t lrow = (lane & 15);
    const uint32_t lcol = (lane >> 4) * 16;

    float c[4][8][4];
#pragma unroll
    for (int i = 0; i < 4; i++)
#pragma unroll
        for (int j = 0; j < 8; j++)
#pragma unroll
            for (int q = 0; q < 4; q++) c[i][j][q] = 0.f;

    const __half* srcAh = Xh + (size_t)m0*EE;
    const __half* srcAl = X1l + (size_t)m0*EE;   // only read when twoTerm
    const __half* srcB  = Wh + (size_t)n0*EE;

    auto load_stage = [&](int s) {
        const int buf = s & 1;
        const uint32_t base = smb + buf * STAGE_BYTES;
        const int k0 = s * BK;
        {
            const __half* src = srcAh + k0;
#pragma unroll
            for (int i = 0; i < 2; i++) {
                int idx = tid + i * 256;
                int r = idx >> 2, ch = idx & 3;
                CP_ASYNC_16(base + r * ROWB + ch * 16, src + (size_t)r * EE + ch * 8);
            }
        }
        if (twoTerm) {
            const __half* src = srcAl + k0;
            const uint32_t dst0 = base + A_BYTES;
#pragma unroll
            for (int i = 0; i < 2; i++) {
                int idx = tid + i * 256;
                int r = idx >> 2, ch = idx & 3;
                CP_ASYNC_16(dst0 + r * ROWB + ch * 16, src + (size_t)r * EE + ch * 8);
            }
        }
        {
            const __half* src = srcB + k0;
            const uint32_t dst0 = base + 2 * A_BYTES;
#pragma unroll
            for (int i = 0; i < 4; i++) {
                int idx = tid + i * 256;
                int r = idx >> 2, ch = idx & 3;
                CP_ASYNC_16(dst0 + r * ROWB + ch * 16, src + (size_t)r * EE + ch * 8);
            }
        }
        CP_COMMIT();
    };

    const int NS = EE / BK;   // 64
    load_stage(0);

    for (int s = 0; s < NS; s++) {
        const int buf = s & 1;
        if (s + 1 < NS) { load_stage(s + 1); CP_WAIT(1); }
        else            { CP_WAIT(0); }
        __syncthreads();

        const uint32_t Ah = smb + buf * STAGE_BYTES;
        const uint32_t Al = Ah + A_BYTES;
        const uint32_t Bh = Ah + 2 * A_BYTES;

#pragma unroll
        for (int kb = 0; kb < BK; kb += 16) {
            const uint32_t kbyte = kb * 2 + lcol;
            uint32_t ah[4][4], al[4][4], bh[8][2];
#pragma unroll
            for (int mt = 0; mt < 4; mt++) {
                const uint32_t ro = (wm + mt * 16 + lrow) * ROWB + kbyte;
                ldsm_x4(ah[mt][0], ah[mt][1], ah[mt][2], ah[mt][3], Ah + ro);
                if (twoTerm)
                    ldsm_x4(al[mt][0], al[mt][1], al[mt][2], al[mt][3], Al + ro);
            }
#pragma unroll
            for (int np = 0; np < 4; np++) {
                const uint32_t ro = (wn + np * 16 + lrow) * ROWB + kbyte;
                uint32_t h0, h1, h2, h3;
                ldsm_x4(h0, h1, h2, h3, Bh + ro);
                bh[2*np][0] = h0; bh[2*np][1] = h2;
                bh[2*np+1][0] = h1; bh[2*np+1][1] = h3;
            }
#pragma unroll
            for (int mt = 0; mt < 4; mt++)
#pragma unroll
                for (int nt = 0; nt < 8; nt++) {
                    mma16816(c[mt][nt], ah[mt], bh[nt]);
                    if (twoTerm) mma16816(c[mt][nt], al[mt], bh[nt]);
                }
        }
        __syncthreads();
    }

    // ---- epilogue per z ----
#pragma unroll
    for (int mt = 0; mt < 4; mt++) {
        const int m = m0 + wm + mt * 16 + g;
        const int bI = m >> 11;
        const int sI = m & (SS - 1);
#pragma unroll
        for (int nt = 0; nt < 8; nt++) {
            const int n = n0 + wn + nt * 8 + 2 * tig;
            const float b0 = bias[n], b1 = bias[n + 1];
            const float y0 = c[mt][nt][0] + b0, y1 = c[mt][nt][1] + b1;
            const float y2 = c[mt][nt][2] + b0, y3 = c[mt][nt][3] + b1;
            const int h = n >> 7, d = n & 127;
            if (z == 0) {
                size_t o0 = (((size_t)(bI * HH + h) * SS + sI) * DD) + d;
                uint32_t lo, hi;
                hi = pack_split_h(y0, y1, lo);
                *(uint32_t*)&Qh[o0] = hi; *(uint32_t*)&Ql[o0] = lo;
                hi = pack_split_h(y2, y3, lo);
                *(uint32_t*)&Qh[o0 + 8 * DD] = hi; *(uint32_t*)&Ql[o0 + 8 * DD] = lo;
            } else if (z == 1) {
                size_t o0 = (((size_t)(bI * HH + h) * SS + sI) * DD) + d;
                *(uint32_t*)&Kh[o0] = pack2_h(y0, y1);
                *(uint32_t*)&Kh[o0 + 8 * DD] = pack2_h(y2, y3);
            } else {
                const size_t base = (size_t)(bI * HH + h) * DD;
                size_t o00 = (base + d) * SS + sI;
                size_t o01 = (base + d + 1) * SS + sI;
                Vh[o00]     = __float2half_rn(y0);
                Vh[o01]     = __float2half_rn(y1);
                Vh[o00 + 8] = __float2half_rn(y2);
                Vh[o01 + 8] = __float2half_rn(y3);
            }
        }
    }
}

// ---------------------------------------------------------------------------
// Output projection GEMM: 2-term A (X1h/X1l), fp32 out. (R12 MODE0)
// ---------------------------------------------------------------------------
__global__ __launch_bounds__(256)
void out_gemm_kernel(const __half* __restrict__ Xh, const __half* __restrict__ Xl,
                     const __half* __restrict__ Wh,
                     const float* __restrict__ bias, float* __restrict__ Yf)
{
    extern __shared__ char sm[];
    const int tid  = threadIdx.x;
    const int lane = tid & 31;
    const int wid  = tid >> 5;
    const int g    = lane >> 2;
    const int tig  = lane & 3;

    const int m0 = blockIdx.y * BM;
    const int n0 = blockIdx.x * BN;
    const int wm = (wid & 1) * 64;
    const int wn = (wid >> 1) * 64;

    const uint32_t smb = smem_u32(sm);
    const uint32_t lrow = (lane & 15);
    const uint32_t lcol = (lane >> 4) * 16;

    float c[4][8][4];
#pragma unroll
    for (int i = 0; i < 4; i++)
#pragma unroll
        for (int j = 0; j < 8; j++)
#pragma unroll
            for (int q = 0; q < 4; q++) c[i][j][q] = 0.f;

    const __half* srcA[2] = { Xh + (size_t)m0*EE, Xl + (size_t)m0*EE };
    const __half* srcB = Wh + (size_t)n0*EE;

    auto load_stage = [&](int s) {
        const int buf = s & 1;
        const uint32_t base = smb + buf * STAGE_BYTES;
        const int k0 = s * BK;
#pragma unroll
        for (int v = 0; v < 2; v++) {
            const __half* src = srcA[v] + k0;
            const uint32_t dst0 = base + v * A_BYTES;
#pragma unroll
            for (int i = 0; i < 2; i++) {
                int idx = tid + i * 256;
                int r = idx >> 2, ch = idx & 3;
                CP_ASYNC_16(dst0 + r * ROWB + ch * 16, src + (size_t)r * EE + ch * 8);
            }
        }
        {
            const __half* src = srcB + k0;
            const uint32_t dst0 = base + 2 * A_BYTES;
#pragma unroll
            for (int i = 0; i < 4; i++) {
                int idx = tid + i * 256;
                int r = idx >> 2, ch = idx & 3;
                CP_ASYNC_16(dst0 + r * ROWB + ch * 16, src + (size_t)r * EE + ch * 8);
            }
        }
        CP_COMMIT();
    };

    const int NS = EE / BK;
    load_stage(0);

    for (int s = 0; s < NS; s++) {
        const int buf = s & 1;
        if (s + 1 < NS) { load_stage(s + 1); CP_WAIT(1); }
        else            { CP_WAIT(0); }
        __syncthreads();

        const uint32_t Ah = smb + buf * STAGE_BYTES;
        const uint32_t Al = Ah + A_BYTES;
        const uint32_t Bh = Ah + 2 * A_BYTES;

#pragma unroll
        for (int kb = 0; kb < BK; kb += 16) {
            const uint32_t kbyte = kb * 2 + lcol;
            uint32_t ah[4][4], al[4][4], bh[8][2];
#pragma unroll
            for (int mt = 0; mt < 4; mt++) {
                const uint32_t ro = (wm + mt * 16 + lrow) * ROWB + kbyte;
                ldsm_x4(ah[mt][0], ah[mt][1], ah[mt][2], ah[mt][3], Ah + ro);
                ldsm_x4(al[mt][0], al[mt][1], al[mt][2], al[mt][3], Al + ro);
            }
#pragma unroll
            for (int np = 0; np < 4; np++) {
                const uint32_t ro = (wn + np * 16 + lrow) * ROWB + kbyte;
                uint32_t h0, h1, h2, h3;
                ldsm_x4(h0, h1, h2, h3, Bh + ro);
                bh[2*np][0] = h0; bh[2*np][1] = h2;
                bh[2*np+1][0] = h1; bh[2*np+1][1] = h3;
            }
#pragma unroll
            for (int mt = 0; mt < 4; mt++)
#pragma unroll
                for (int nt = 0; nt < 8; nt++) {
                    mma16816(c[mt][nt], ah[mt], bh[nt]);
                    mma16816(c[mt][nt], al[mt], bh[nt]);
                }
        }
        __syncthreads();
    }

#pragma unroll
    for (int mt = 0; mt < 4; mt++) {
        const int m = m0 + wm + mt * 16 + g;
#pragma unroll
        for (int nt = 0; nt < 8; nt++) {
            const int n = n0 + wn + nt * 8 + 2 * tig;
            const float b0 = bias[n], b1 = bias[n + 1];
            size_t o0 = (size_t)m * EE + n;
            float2 v0; v0.x = c[mt][nt][0] + b0; v0.y = c[mt][nt][1] + b1;
            float2 v1; v1.x = c[mt][nt][2] + b0; v1.y = c[mt][nt][3] + b1;
            *(float2*)&Yf[o0] = v0;
            *(float2*)&Yf[o0 + 8 * EE] = v1;
        }
    }
}

// ---------------------------------------------------------------------------
// Flash attention: Q split (2-term QK), K single, V single, PV single-term P.
// ---------------------------------------------------------------------------
#define AQT 128
#define AKT 64
#define ROWK 272
#define ROWV 144
#define KH_BYTES (64*ROWK)          // 17408
#define VH_BYTES (128*ROWV)         // 18432
#define KV_STAGE (KH_BYTES + VH_BYTES)   // 35840
#define ATTN_SMEM (2*KV_STAGE)           // 71680

__global__ __launch_bounds__(256)
void attn_mma_kernel(const __half* __restrict__ Qh_, const __half* __restrict__ Ql_,
                     const __half* __restrict__ Kh_, const __half* __restrict__ Vh_,
                     __half* __restrict__ Xh, __half* __restrict__ Xl)
{
    extern __shared__ char sm[];
    const uint32_t smb = smem_u32(sm);
    const int tid  = threadIdx.x;
    const int lane = tid & 31;
    const int wid  = tid >> 5;
    const int g    = lane >> 2;
    const int tig  = lane & 3;
    const uint32_t lrow = (lane & 15);
    const uint32_t lcol = (lane >> 4) * 16;

    const int bh = blockIdx.y;
    const int q0 = blockIdx.x * AQT;
    const size_t hoff = (size_t)bh * SS * DD;

    const __half* ksrc = Kh_ + hoff;
    const __half* vsrc = Vh_ + (size_t)bh * DD * SS;

    // ---- Q tile (hi/lo) to smem, fragments via ldmatrix ----
    {
        const __half* qsrc[2] = { Qh_ + hoff + (size_t)q0 * DD,
                                  Ql_ + hoff + (size_t)q0 * DD };
#pragma unroll
        for (int v = 0; v < 2; v++) {
            const uint32_t dst0 = smb + v * (128 * ROWK);
#pragma unroll
            for (int i = 0; i < 8; i++) {
                int idx = tid + i * 256;
                int row = idx >> 4, ch = idx & 15;
                CP_ASYNC_16(dst0 + row * ROWK + ch * 16, qsrc[v] + (size_t)row * DD + ch * 8);
            }
        }
        CP_COMMIT(); CP_WAIT(0);
        __syncthreads();
    }

    uint32_t qh[8][4], ql[8][4];
    {
        const uint32_t ro = (wid * 16 + lrow) * ROWK + lcol;
#pragma unroll
        for (int ks = 0; ks < 8; ks++) {
            ldsm_x4(qh[ks][0], qh[ks][1], qh[ks][2], qh[ks][3], smb + ro + ks * 32);
            ldsm_x4(ql[ks][0], ql[ks][1], ql[ks][2], ql[ks][3],
                    smb + 128 * ROWK + ro + ks * 32);
        }
    }
    __syncthreads();

    auto load_kv = [&](int it) {
        const uint32_t base = smb + (it & 1) * KV_STAGE;
        const int kt = it * AKT;
#pragma unroll
        for (int i = 0; i < 4; i++) {
            int idx = tid + i * 256;
            int row = idx >> 4, ch = idx & 15;
            CP_ASYNC_16(base + row * ROWK + ch * 16,
                        ksrc + (size_t)(kt + row) * DD + ch * 8);
        }
        {
            const uint32_t dst0 = base + KH_BYTES;
#pragma unroll
            for (int i = 0; i < 4; i++) {
                int idx = tid + i * 256;
                int row = idx >> 3, ch = idx & 7;
                CP_ASYNC_16(dst0 + row * ROWV + ch * 16,
                            vsrc + (size_t)row * SS + kt + ch * 8);
            }
        }
        CP_COMMIT();
    };

    const float scale = 0.08838834764831845f;
    float m0 = -INFINITY, m1 = -INFINITY, l0 = 0.f, l1 = 0.f;
    float o[16][4];
#pragma unroll
    for (int dt = 0; dt < 16; dt++)
#pragma unroll
        for (int q = 0; q < 4; q++) o[dt][q] = 0.f;

    const int NIT = SS / AKT;
    load_kv(0);

    for (int it = 0; it < NIT; it++) {
        if (it + 1 < NIT) { load_kv(it + 1); CP_WAIT(1); }
        else              { CP_WAIT(0); }
        __syncthreads();

        const uint32_t smK = smb + (it & 1) * KV_STAGE;
        const uint32_t smV = smK + KH_BYTES;

        // ---- scores: (Qh + Ql) x K ----
        float sc[8][4];
#pragma unroll
        for (int nt = 0; nt < 8; nt++)
#pragma unroll
            for (int q = 0; q < 4; q++) sc[nt][q] = 0.f;

#pragma unroll
        for (int ks = 0; ks < 8; ks++) {
#pragma unroll
            for (int np = 0; np < 4; np++) {
                const uint32_t ro = (np * 16 + lrow) * ROWK + ks * 32 + lcol;
                uint32_t h0, h1, h2, h3;
                ldsm_x4(h0, h1, h2, h3, smK + ro);
                uint32_t b0h[2] = { h0, h2 }, b1h[2] = { h1, h3 };
                mma16816(sc[2*np],   qh[ks], b0h);
                mma16816(sc[2*np],   ql[ks], b0h);
                mma16816(sc[2*np+1], qh[ks], b1h);
                mma16816(sc[2*np+1], ql[ks], b1h);
            }
        }

        // ---- online softmax ----
        float mx0 = -INFINITY, mx1 = -INFINITY;
#pragma unroll
        for (int nt = 0; nt < 8; nt++) {
            mx0 = fmaxf(mx0, fmaxf(sc[nt][0], sc[nt][1]));
            mx1 = fmaxf(mx1, fmaxf(sc[nt][2], sc[nt][3]));
        }
        mx0 = fmaxf(mx0, __shfl_xor_sync(0xffffffffu, mx0, 1));
        mx0 = fmaxf(mx0, __shfl_xor_sync(0xffffffffu, mx0, 2));
        mx1 = fmaxf(mx1, __shfl_xor_sync(0xffffffffu, mx1, 1));
        mx1 = fmaxf(mx1, __shfl_xor_sync(0xffffffffu, mx1, 2));

        const float mn0 = fmaxf(m0, mx0 * scale);
        const float mn1 = fmaxf(m1, mx1 * scale);
        const float a0 = __expf(m0 - mn0);
        const float a1 = __expf(m1 - mn1);
        m0 = mn0; m1 = mn1;

        float rs0 = 0.f, rs1 = 0.f;
        uint32_t ph[8][2];
#pragma unroll
        for (int nt = 0; nt < 8; nt++) {
            float p0 = __expf(sc[nt][0] * scale - mn0);
            float p1 = __expf(sc[nt][1] * scale - mn0);
            float p2 = __expf(sc[nt][2] * scale - mn1);
            float p3 = __expf(sc[nt][3] * scale - mn1);
            rs0 += p0 + p1; rs1 += p2 + p3;
            ph[nt][0] = pack2_h(p0, p1);
            ph[nt][1] = pack2_h(p2, p3);
        }
        rs0 += __shfl_xor_sync(0xffffffffu, rs0, 1);
        rs0 += __shfl_xor_sync(0xffffffffu, rs0, 2);
        rs1 += __shfl_xor_sync(0xffffffffu, rs1, 1);
        rs1 += __shfl_xor_sync(0xffffffffu, rs1, 2);
        l0 = l0 * a0 + rs0;
        l1 = l1 * a1 + rs1;

#pragma unroll
        for (int dt = 0; dt < 16; dt++) {
            o[dt][0] *= a0; o[dt][1] *= a0;
            o[dt][2] *= a1; o[dt][3] *= a1;
        }

        // ---- PV: single-term P x V ----
#pragma unroll
        for (int ks = 0; ks < 4; ks++) {
            uint32_t ah[4] = { ph[2*ks][0], ph[2*ks][1], ph[2*ks+1][0], ph[2*ks+1][1] };
#pragma unroll
            for (int dp = 0; dp < 8; dp++) {
                const uint32_t ro = (dp * 16 + lrow) * ROWV + ks * 32 + lcol;
                uint32_t h0, h1, h2, h3;
                ldsm_x4(h0, h1, h2, h3, smV + ro);
                uint32_t b0h[2] = { h0, h2 }, b1h[2] = { h1, h3 };
                mma16816(o[2*dp],   ah, b0h);
                mma16816(o[2*dp+1], ah, b1h);
            }
        }
        __syncthreads();
    }

    // ---- epilogue: normalize, split fp16, store ----
    const float inv0 = 1.0f / l0;
    const float inv1 = 1.0f / l1;
    const int bI = bh >> 4;
    const int h  = bh & 15;
    const int row0 = q0 + wid * 16 + g;
#pragma unroll
    for (int dt = 0; dt < 16; dt++) {
        const int e = h * 128 + dt * 8 + 2 * tig;
        size_t adr0 = (size_t)(bI * SS + row0) * EE + e;
        size_t adr1 = adr0 + (size_t)8 * EE;
        uint32_t lo, hi;
        hi = pack_split_h(o[dt][0] * inv0, o[dt][1] * inv0, lo);
        *(uint32_t*)&Xh[adr0] = hi; *(uint32_t*)&Xl[adr0] = lo;
        hi = pack_split_h(o[dt][2] * inv1, o[dt][3] * inv1, lo);
        *(uint32_t*)&Xh[adr1] = hi; *(uint32_t*)&Xl[adr1] = lo;
    }
}

// ---------------------------------------------------------------------------
extern "C" void kernel_launch(void* const* d_in, const int* in_sizes, int n_in,
                              void* d_out, int out_size)
{
    const float* query  = (const float*)d_in[0];
    const float* key_in = (const float*)d_in[1];
    const float* value  = (const float*)d_in[2];
    const float* Wq = (const float*)d_in[3];
    const float* bq = (const float*)d_in[4];
    const float* Wk = (const float*)d_in[5];
    const float* bk = (const float*)d_in[6];
    const float* Wv = (const float*)d_in[7];
    const float* bv = (const float*)d_in[8];
    const float* Wo = (const float*)d_in[9];
    const float* bo = (const float*)d_in[10];
    float* out = (float*)d_out;

    __half *Qh, *Ql, *Kh, *Vh;
    __half *X1h, *X1l, *X2h, *X3h, *Wth;
    cudaGetSymbolAddress((void**)&Qh, g_Qh);
    cudaGetSymbolAddress((void**)&Ql, g_Ql);
    cudaGetSymbolAddress((void**)&Kh, g_Kh);
    cudaGetSymbolAddress((void**)&Vh, g_Vh);
    cudaGetSymbolAddress((void**)&X1h, g_X1h);
    cudaGetSymbolAddress((void**)&X1l, g_X1l);
    cudaGetSymbolAddress((void**)&X2h, g_X2h);
    cudaGetSymbolAddress((void**)&X3h, g_X3h);
    cudaGetSymbolAddress((void**)&Wth, g_Wth);

    cudaFuncSetAttribute(qkv_gemm_kernel, cudaFuncAttributeMaxDynamicSharedMemorySize, GEMM_SMEM);
    cudaFuncSetAttribute(out_gemm_kernel, cudaFuncAttributeMaxDynamicSharedMemorySize, GEMM_SMEM);
    cudaFuncSetAttribute(attn_mma_kernel, cudaFuncAttributeMaxDynamicSharedMemorySize, ATTN_SMEM);

    const int n4 = MROWS * EE / 4;
    const size_t WSZ = (size_t)EE * EE;
    dim3 gt(EE/32, EE/32, 4), bt(32, 32);
    dim3 gs(1024, 3);

    split3_kernel<<<gs, 256>>>(query, key_in, value, X1h, X1l, X2h, X3h, n4);
    transpose4_kernel<<<gt, bt>>>(Wq, Wk, Wv, Wo, Wth);

    // batched Q/K/V projections (z = 0,1,2)
    dim3 gqkv(EE/BN, MROWS/BM, 3);     // (8, 32, 3) = 768 blocks
    qkv_gemm_kernel<<<gqkv, 256, GEMM_SMEM>>>(X1h, X1l, X2h, X3h, Wth,
                                              bq, bk, bv, Qh, Ql, Kh, Vh);

    dim3 ga(SS/AQT, BB*HH);            // (16, 32)
    attn_mma_kernel<<<ga, 256, ATTN_SMEM>>>(Qh, Ql, Kh, Vh, X1h, X1l);

    dim3 gg(EE/BN, MROWS/BM);          // (8, 32)
    out_gemm_kernel<<<gg, 256, GEMM_SMEM>>>(X1h, X1l, Wth + 3*WSZ, bo, out);
}

// round 14
// speedup vs baseline: 3.1902x; 1.2825x over previous
#include <cuda_runtime.h>
#include <cuda_fp16.h>
#include <cstdint>
#include <math.h>

#define BB 2
#define SS 2048
#define EE 2048
#define HH 16
#define DD 128
#define MROWS (BB*SS)   // 4096

// ---------------- device scratch (fp16) ----------------
__device__ __half g_Qh[MROWS*EE];  // [B*H, S, D] single
__device__ __half g_Kh[MROWS*EE];  // [B*H, S, D] single
__device__ __half g_Vh[MROWS*EE];  // [B*H, D, S] single (transposed)
__device__ __half g_X1h[MROWS*EE]; // query input single / attn-out hi
__device__ __half g_X1l[MROWS*EE]; // attn-out lo
__device__ __half g_X2h[MROWS*EE];
__device__ __half g_X3h[MROWS*EE];
__device__ __half g_Wth[4*EE*EE];  // 4 weights, W^T single fp16 [n][k]

// ---------------- primitives ----------------
__device__ __forceinline__ uint32_t smem_u32(const void* p) {
    uint32_t a;
    asm("{ .reg .u64 t; cvta.to.shared.u64 t, %1; cvt.u32.u64 %0, t; }" : "=r"(a) : "l"(p));
    return a;
}
#define CP_ASYNC_16(dst_u32, src_ptr) \
    asm volatile("cp.async.cg.shared.global [%0], [%1], 16;" :: "r"(dst_u32), "l"(src_ptr))
#define CP_COMMIT() asm volatile("cp.async.commit_group;" ::: "memory")
#define CP_WAIT(n)  asm volatile("cp.async.wait_group %0;" :: "n"(n) : "memory")

__device__ __forceinline__ void mma16816(float* c, const uint32_t* a, const uint32_t* b) {
    asm volatile(
        "mma.sync.aligned.m16n8k16.row.col.f32.f16.f16.f32 "
        "{%0,%1,%2,%3}, {%4,%5,%6,%7}, {%8,%9}, {%0,%1,%2,%3};"
        : "+f"(c[0]), "+f"(c[1]), "+f"(c[2]), "+f"(c[3])
        : "r"(a[0]), "r"(a[1]), "r"(a[2]), "r"(a[3]), "r"(b[0]), "r"(b[1]));
}

__device__ __forceinline__ void ldsm_x4(uint32_t& r0, uint32_t& r1, uint32_t& r2,
                                        uint32_t& r3, uint32_t addr) {
    asm volatile("ldmatrix.sync.aligned.m8n8.x4.shared.b16 {%0,%1,%2,%3}, [%4];"
                 : "=r"(r0), "=r"(r1), "=r"(r2), "=r"(r3) : "r"(addr));
}

__device__ __forceinline__ uint32_t pack_split_h(float x, float y, uint32_t& lo) {
    __half hx = __float2half_rn(x), hy = __float2half_rn(y);
    __half lx = __float2half_rn(x - __half2float(hx));
    __half ly = __float2half_rn(y - __half2float(hy));
    __half2 hp; hp.x = hx; hp.y = hy;
    __half2 lp; lp.x = lx; lp.y = ly;
    lo = *(uint32_t*)&lp;
    return *(uint32_t*)&hp;
}
__device__ __forceinline__ uint32_t pack2_h(float x, float y) {
    __half2 p; p.x = __float2half_rn(x); p.y = __float2half_rn(y);
    return *(uint32_t*)&p;
}

// ---------------------------------------------------------------------------
// Conversion kernels: all three inputs -> single fp16
// ---------------------------------------------------------------------------
__global__ __launch_bounds__(256)
void split3_kernel(const float* __restrict__ X0, const float* __restrict__ X1,
                   const float* __restrict__ X2,
                   __half* __restrict__ H0, __half* __restrict__ H1,
                   __half* __restrict__ H2, int n4)
{
    const int z = blockIdx.y;
    const float* X = (z == 0) ? X0 : (z == 1) ? X1 : X2;
    __half* H = (z == 0) ? H0 : (z == 1) ? H1 : H2;
    int i = blockIdx.x * blockDim.x + threadIdx.x;
    const int stride = gridDim.x * blockDim.x;
    for (; i < n4; i += stride) {
        float4 v = ((const float4*)X)[i];
        ((uint32_t*)H)[2*i]   = pack2_h(v.x, v.y);
        ((uint32_t*)H)[2*i+1] = pack2_h(v.z, v.w);
    }
}

__global__ __launch_bounds__(1024)
void transpose4_kernel(const float* __restrict__ W0, const float* __restrict__ W1,
                       const float* __restrict__ W2, const float* __restrict__ W3,
                       __half* __restrict__ Th)
{
    __shared__ float t[32][33];
    const int z = blockIdx.z;
    const float* W = (z == 0) ? W0 : (z == 1) ? W1 : (z == 2) ? W2 : W3;
    __half* TH = Th + (size_t)z * EE * EE;
    const int n0 = blockIdx.x * 32, k0 = blockIdx.y * 32;
    const int tx = threadIdx.x, ty = threadIdx.y;
    t[ty][tx] = W[(size_t)(k0 + ty) * EE + n0 + tx];
    __syncthreads();
    TH[(size_t)(n0 + ty) * EE + k0 + tx] = __float2half_rn(t[tx][ty]);
}

// ---------------------------------------------------------------------------
// Shared GEMM geometry
// ---------------------------------------------------------------------------
#define BM 128
#define BN 256
#define BK 32
#define ROWB 112
#define A_BYTES (BM*ROWB)              // 14336
#define B_BYTES (BN*ROWB)              // 28672

// single-term stage (qkv): A + B
#define STAGE1 (A_BYTES + B_BYTES)     // 43008
#define QKV_SMEM (2*STAGE1)            // 86016
// 2-term stage (out): Ah + Al + B
#define STAGE2 (2*A_BYTES + B_BYTES)   // 57344
#define OUT_SMEM (2*STAGE2)            // 114688

// ---------------------------------------------------------------------------
// Batched QKV projection GEMM, all single-term.
// blockIdx.z: 0=Q (head-major), 1=K (head-major), 2=V (transposed).
// ---------------------------------------------------------------------------
__global__ __launch_bounds__(256)
void qkv_gemm_kernel(const __half* __restrict__ X1h, const __half* __restrict__ X2h,
                     const __half* __restrict__ X3h, const __half* __restrict__ Wt,
                     const float* __restrict__ bq, const float* __restrict__ bk,
                     const float* __restrict__ bv,
                     __half* __restrict__ Qh, __half* __restrict__ Kh,
                     __half* __restrict__ Vh)
{
    extern __shared__ char sm[];
    const int z = blockIdx.z;
    const __half* Xh = (z == 0) ? X1h : (z == 1) ? X2h : X3h;
    const __half* Wh = Wt + (size_t)z * EE * EE;
    const float* bias = (z == 0) ? bq : (z == 1) ? bk : bv;
    __half* Yh = (z == 0) ? Qh : (z == 1) ? Kh : Vh;

    const int tid  = threadIdx.x;
    const int lane = tid & 31;
    const int wid  = tid >> 5;
    const int g    = lane >> 2;
    const int tig  = lane & 3;

    const int m0 = blockIdx.y * BM;
    const int n0 = blockIdx.x * BN;
    const int wm = (wid & 1) * 64;
    const int wn = (wid >> 1) * 64;

    const uint32_t smb = smem_u32(sm);
    const uint32_t lrow = (lane & 15);
    const uint32_t lcol = (lane >> 4) * 16;

    float c[4][8][4];
#pragma unroll
    for (int i = 0; i < 4; i++)
#pragma unroll
        for (int j = 0; j < 8; j++)
#pragma unroll
            for (int q = 0; q < 4; q++) c[i][j][q] = 0.f;

    const __half* srcA = Xh + (size_t)m0*EE;
    const __half* srcB = Wh + (size_t)n0*EE;

    auto load_stage = [&](int s) {
        const int buf = s & 1;
        const uint32_t base = smb + buf * STAGE1;
        const int k0 = s * BK;
        {
            const __half* src = srcA + k0;
#pragma unroll
            for (int i = 0; i < 2; i++) {
                int idx = tid + i * 256;
                int r = idx >> 2, ch = idx & 3;
                CP_ASYNC_16(base + r * ROWB + ch * 16, src + (size_t)r * EE + ch * 8);
            }
        }
        {
            const __half* src = srcB + k0;
            const uint32_t dst0 = base + A_BYTES;
#pragma unroll
            for (int i = 0; i < 4; i++) {
                int idx = tid + i * 256;
                int r = idx >> 2, ch = idx & 3;
                CP_ASYNC_16(dst0 + r * ROWB + ch * 16, src + (size_t)r * EE + ch * 8);
            }
        }
        CP_COMMIT();
    };

    const int NS = EE / BK;   // 64
    load_stage(0);

    for (int s = 0; s < NS; s++) {
        const int buf = s & 1;
        if (s + 1 < NS) { load_stage(s + 1); CP_WAIT(1); }
        else            { CP_WAIT(0); }
        __syncthreads();

        const uint32_t Ah = smb + buf * STAGE1;
        const uint32_t Bh = Ah + A_BYTES;

#pragma unroll
        for (int kb = 0; kb < BK; kb += 16) {
            const uint32_t kbyte = kb * 2 + lcol;
            uint32_t ah[4][4], bh[8][2];
#pragma unroll
            for (int mt = 0; mt < 4; mt++) {
                const uint32_t ro = (wm + mt * 16 + lrow) * ROWB + kbyte;
                ldsm_x4(ah[mt][0], ah[mt][1], ah[mt][2], ah[mt][3], Ah + ro);
            }
#pragma unroll
            for (int np = 0; np < 4; np++) {
                const uint32_t ro = (wn + np * 16 + lrow) * ROWB + kbyte;
                uint32_t h0, h1, h2, h3;
                ldsm_x4(h0, h1, h2, h3, Bh + ro);
                bh[2*np][0] = h0; bh[2*np][1] = h2;
                bh[2*np+1][0] = h1; bh[2*np+1][1] = h3;
            }
#pragma unroll
            for (int mt = 0; mt < 4; mt++)
#pragma unroll
                for (int nt = 0; nt < 8; nt++)
                    mma16816(c[mt][nt], ah[mt], bh[nt]);
        }
        __syncthreads();
    }

    // ---- epilogue per z ----
#pragma unroll
    for (int mt = 0; mt < 4; mt++) {
        const int m = m0 + wm + mt * 16 + g;
        const int bI = m >> 11;
        const int sI = m & (SS - 1);
#pragma unroll
        for (int nt = 0; nt < 8; nt++) {
            const int n = n0 + wn + nt * 8 + 2 * tig;
            const float b0 = bias[n], b1 = bias[n + 1];
            const float y0 = c[mt][nt][0] + b0, y1 = c[mt][nt][1] + b1;
            const float y2 = c[mt][nt][2] + b0, y3 = c[mt][nt][3] + b1;
            const int h = n >> 7, d = n & 127;
            if (z != 2) {
                size_t o0 = (((size_t)(bI * HH + h) * SS + sI) * DD) + d;
                *(uint32_t*)&Yh[o0] = pack2_h(y0, y1);
                *(uint32_t*)&Yh[o0 + 8 * DD] = pack2_h(y2, y3);
            } else {
                const size_t base = (size_t)(bI * HH + h) * DD;
                size_t o00 = (base + d) * SS + sI;
                size_t o01 = (base + d + 1) * SS + sI;
                Yh[o00]     = __float2half_rn(y0);
                Yh[o01]     = __float2half_rn(y1);
                Yh[o00 + 8] = __float2half_rn(y2);
                Yh[o01 + 8] = __float2half_rn(y3);
            }
        }
    }
}

// ---------------------------------------------------------------------------
// Output projection GEMM: 2-term A (attn-out hi/lo), fp32 out.
// ---------------------------------------------------------------------------
__global__ __launch_bounds__(256)
void out_gemm_kernel(const __half* __restrict__ Xh, const __half* __restrict__ Xl,
                     const __half* __restrict__ Wh,
                     const float* __restrict__ bias, float* __restrict__ Yf)
{
    extern __shared__ char sm[];
    const int tid  = threadIdx.x;
    const int lane = tid & 31;
    const int wid  = tid >> 5;
    const int g    = lane >> 2;
    const int tig  = lane & 3;

    const int m0 = blockIdx.y * BM;
    const int n0 = blockIdx.x * BN;
    const int wm = (wid & 1) * 64;
    const int wn = (wid >> 1) * 64;

    const uint32_t smb = smem_u32(sm);
    const uint32_t lrow = (lane & 15);
    const uint32_t lcol = (lane >> 4) * 16;

    float c[4][8][4];
#pragma unroll
    for (int i = 0; i < 4; i++)
#pragma unroll
        for (int j = 0; j < 8; j++)
#pragma unroll
            for (int q = 0; q < 4; q++) c[i][j][q] = 0.f;

    const __half* srcA[2] = { Xh + (size_t)m0*EE, Xl + (size_t)m0*EE };
    const __half* srcB = Wh + (size_t)n0*EE;

    auto load_stage = [&](int s) {
        const int buf = s & 1;
        const uint32_t base = smb + buf * STAGE2;
        const int k0 = s * BK;
#pragma unroll
        for (int v = 0; v < 2; v++) {
            const __half* src = srcA[v] + k0;
            const uint32_t dst0 = base + v * A_BYTES;
#pragma unroll
            for (int i = 0; i < 2; i++) {
                int idx = tid + i * 256;
                int r = idx >> 2, ch = idx & 3;
                CP_ASYNC_16(dst0 + r * ROWB + ch * 16, src + (size_t)r * EE + ch * 8);
            }
        }
        {
            const __half* src = srcB + k0;
            const uint32_t dst0 = base + 2 * A_BYTES;
#pragma unroll
            for (int i = 0; i < 4; i++) {
                int idx = tid + i * 256;
                int r = idx >> 2, ch = idx & 3;
                CP_ASYNC_16(dst0 + r * ROWB + ch * 16, src + (size_t)r * EE + ch * 8);
            }
        }
        CP_COMMIT();
    };

    const int NS = EE / BK;
    load_stage(0);

    for (int s = 0; s < NS; s++) {
        const int buf = s & 1;
        if (s + 1 < NS) { load_stage(s + 1); CP_WAIT(1); }
        else            { CP_WAIT(0); }
        __syncthreads();

        const uint32_t Ah = smb + buf * STAGE2;
        const uint32_t Al = Ah + A_BYTES;
        const uint32_t Bh = Ah + 2 * A_BYTES;

#pragma unroll
        for (int kb = 0; kb < BK; kb += 16) {
            const uint32_t kbyte = kb * 2 + lcol;
            uint32_t ah[4][4], al[4][4], bh[8][2];
#pragma unroll
            for (int mt = 0; mt < 4; mt++) {
                const uint32_t ro = (wm + mt * 16 + lrow) * ROWB + kbyte;
                ldsm_x4(ah[mt][0], ah[mt][1], ah[mt][2], ah[mt][3], Ah + ro);
                ldsm_x4(al[mt][0], al[mt][1], al[mt][2], al[mt][3], Al + ro);
            }
#pragma unroll
            for (int np = 0; np < 4; np++) {
                const uint32_t ro = (wn + np * 16 + lrow) * ROWB + kbyte;
                uint32_t h0, h1, h2, h3;
                ldsm_x4(h0, h1, h2, h3, Bh + ro);
                bh[2*np][0] = h0; bh[2*np][1] = h2;
                bh[2*np+1][0] = h1; bh[2*np+1][1] = h3;
            }
#pragma unroll
            for (int mt = 0; mt < 4; mt++)
#pragma unroll
                for (int nt = 0; nt < 8; nt++) {
                    mma16816(c[mt][nt], ah[mt], bh[nt]);
                    mma16816(c[mt][nt], al[mt], bh[nt]);
                }
        }
        __syncthreads();
    }

#pragma unroll
    for (int mt = 0; mt < 4; mt++) {
        const int m = m0 + wm + mt * 16 + g;
#pragma unroll
        for (int nt = 0; nt < 8; nt++) {
            const int n = n0 + wn + nt * 8 + 2 * tig;
            const float b0 = bias[n], b1 = bias[n + 1];
            size_t o0 = (size_t)m * EE + n;
            float2 v0; v0.x = c[mt][nt][0] + b0; v0.y = c[mt][nt][1] + b1;
            float2 v1; v1.x = c[mt][nt][2] + b0; v1.y = c[mt][nt][3] + b1;
            *(float2*)&Yf[o0] = v0;
            *(float2*)&Yf[o0 + 8 * EE] = v1;
        }
    }
}

// ---------------------------------------------------------------------------
// Flash attention: Q/K/V single fp16, single-term QK and PV; split output.
// ---------------------------------------------------------------------------
#define AQT 128
#define AKT 64
#define ROWK 272
#define ROWV 144
#define KH_BYTES (64*ROWK)          // 17408
#define VH_BYTES (128*ROWV)         // 18432
#define KV_STAGE (KH_BYTES + VH_BYTES)   // 35840
#define ATTN_SMEM (2*KV_STAGE)           // 71680 (Q phase 34816 fits)

__global__ __launch_bounds__(256)
void attn_mma_kernel(const __half* __restrict__ Qh_, const __half* __restrict__ Kh_,
                     const __half* __restrict__ Vh_,
                     __half* __restrict__ Xh, __half* __restrict__ Xl)
{
    extern __shared__ char sm[];
    const uint32_t smb = smem_u32(sm);
    const int tid  = threadIdx.x;
    const int lane = tid & 31;
    const int wid  = tid >> 5;
    const int g    = lane >> 2;
    const int tig  = lane & 3;
    const uint32_t lrow = (lane & 15);
    const uint32_t lcol = (lane >> 4) * 16;

    const int bh = blockIdx.y;
    const int q0 = blockIdx.x * AQT;
    const size_t hoff = (size_t)bh * SS * DD;

    const __half* ksrc = Kh_ + hoff;
    const __half* vsrc = Vh_ + (size_t)bh * DD * SS;

    // ---- Q tile (single) to smem, fragments via ldmatrix ----
    {
        const __half* qsrc = Qh_ + hoff + (size_t)q0 * DD;
#pragma unroll
        for (int i = 0; i < 8; i++) {
            int idx = tid + i * 256;
            int row = idx >> 4, ch = idx & 15;
            CP_ASYNC_16(smb + row * ROWK + ch * 16, qsrc + (size_t)row * DD + ch * 8);
        }
        CP_COMMIT(); CP_WAIT(0);
        __syncthreads();
    }

    uint32_t qh[8][4];
    {
        const uint32_t ro = (wid * 16 + lrow) * ROWK + lcol;
#pragma unroll
        for (int ks = 0; ks < 8; ks++)
            ldsm_x4(qh[ks][0], qh[ks][1], qh[ks][2], qh[ks][3], smb + ro + ks * 32);
    }
    __syncthreads();

    auto load_kv = [&](int it) {
        const uint32_t base = smb + (it & 1) * KV_STAGE;
        const int kt = it * AKT;
#pragma unroll
        for (int i = 0; i < 4; i++) {
            int idx = tid + i * 256;
            int row = idx >> 4, ch = idx & 15;
            CP_ASYNC_16(base + row * ROWK + ch * 16,
                        ksrc + (size_t)(kt + row) * DD + ch * 8);
        }
        {
            const uint32_t dst0 = base + KH_BYTES;
#pragma unroll
            for (int i = 0; i < 4; i++) {
                int idx = tid + i * 256;
                int row = idx >> 3, ch = idx & 7;
                CP_ASYNC_16(dst0 + row * ROWV + ch * 16,
                            vsrc + (size_t)row * SS + kt + ch * 8);
            }
        }
        CP_COMMIT();
    };

    const float scale = 0.08838834764831845f;
    float m0 = -INFINITY, m1 = -INFINITY, l0 = 0.f, l1 = 0.f;
    float o[16][4];
#pragma unroll
    for (int dt = 0; dt < 16; dt++)
#pragma unroll
        for (int q = 0; q < 4; q++) o[dt][q] = 0.f;

    const int NIT = SS / AKT;
    load_kv(0);

    for (int it = 0; it < NIT; it++) {
        if (it + 1 < NIT) { load_kv(it + 1); CP_WAIT(1); }
        else              { CP_WAIT(0); }
        __syncthreads();

        const uint32_t smK = smb + (it & 1) * KV_STAGE;
        const uint32_t smV = smK + KH_BYTES;

        // ---- scores: single-term Q x K ----
        float sc[8][4];
#pragma unroll
        for (int nt = 0; nt < 8; nt++)
#pragma unroll
            for (int q = 0; q < 4; q++) sc[nt][q] = 0.f;

#pragma unroll
        for (int ks = 0; ks < 8; ks++) {
#pragma unroll
            for (int np = 0; np < 4; np++) {
                const uint32_t ro = (np * 16 + lrow) * ROWK + ks * 32 + lcol;
                uint32_t h0, h1, h2, h3;
                ldsm_x4(h0, h1, h2, h3, smK + ro);
                uint32_t b0h[2] = { h0, h2 }, b1h[2] = { h1, h3 };
                mma16816(sc[2*np],   qh[ks], b0h);
                mma16816(sc[2*np+1], qh[ks], b1h);
            }
        }

        // ---- online softmax ----
        float mx0 = -INFINITY, mx1 = -INFINITY;
#pragma unroll
        for (int nt = 0; nt < 8; nt++) {
            mx0 = fmaxf(mx0, fmaxf(sc[nt][0], sc[nt][1]));
            mx1 = fmaxf(mx1, fmaxf(sc[nt][2], sc[nt][3]));
        }
        mx0 = fmaxf(mx0, __shfl_xor_sync(0xffffffffu, mx0, 1));
        mx0 = fmaxf(mx0, __shfl_xor_sync(0xffffffffu, mx0, 2));
        mx1 = fmaxf(mx1, __shfl_xor_sync(0xffffffffu, mx1, 1));
        mx1 = fmaxf(mx1, __shfl_xor_sync(0xffffffffu, mx1, 2));

        const float mn0 = fmaxf(m0, mx0 * scale);
        const float mn1 = fmaxf(m1, mx1 * scale);
        const float a0 = __expf(m0 - mn0);
        const float a1 = __expf(m1 - mn1);
        m0 = mn0; m1 = mn1;

        float rs0 = 0.f, rs1 = 0.f;
        uint32_t ph[8][2];
#pragma unroll
        for (int nt = 0; nt < 8; nt++) {
            float p0 = __expf(sc[nt][0] * scale - mn0);
            float p1 = __expf(sc[nt][1] * scale - mn0);
            float p2 = __expf(sc[nt][2] * scale - mn1);
            float p3 = __expf(sc[nt][3] * scale - mn1);
            rs0 += p0 + p1; rs1 += p2 + p3;
            ph[nt][0] = pack2_h(p0, p1);
            ph[nt][1] = pack2_h(p2, p3);
        }
        rs0 += __shfl_xor_sync(0xffffffffu, rs0, 1);
        rs0 += __shfl_xor_sync(0xffffffffu, rs0, 2);
        rs1 += __shfl_xor_sync(0xffffffffu, rs1, 1);
        rs1 += __shfl_xor_sync(0xffffffffu, rs1, 2);
        l0 = l0 * a0 + rs0;
        l1 = l1 * a1 + rs1;

#pragma unroll
        for (int dt = 0; dt < 16; dt++) {
            o[dt][0] *= a0; o[dt][1] *= a0;
            o[dt][2] *= a1; o[dt][3] *= a1;
        }

        // ---- PV: single-term P x V ----
#pragma unroll
        for (int ks = 0; ks < 4; ks++) {
            uint32_t ah[4] = { ph[2*ks][0], ph[2*ks][1], ph[2*ks+1][0], ph[2*ks+1][1] };
#pragma unroll
            for (int dp = 0; dp < 8; dp++) {
                const uint32_t ro = (dp * 16 + lrow) * ROWV + ks * 32 + lcol;
                uint32_t h0, h1, h2, h3;
                ldsm_x4(h0, h1, h2, h3, smV + ro);
                uint32_t b0h[2] = { h0, h2 }, b1h[2] = { h1, h3 };
                mma16816(o[2*dp],   ah, b0h);
                mma16816(o[2*dp+1], ah, b1h);
            }
        }
        __syncthreads();
    }

    // ---- epilogue: normalize, split fp16, store ----
    const float inv0 = 1.0f / l0;
    const float inv1 = 1.0f / l1;
    const int bI = bh >> 4;
    const int h  = bh & 15;
    const int row0 = q0 + wid * 16 + g;
#pragma unroll
    for (int dt = 0; dt < 16; dt++) {
        const int e = h * 128 + dt * 8 + 2 * tig;
        size_t adr0 = (size_t)(bI * SS + row0) * EE + e;
        size_t adr1 = adr0 + (size_t)8 * EE;
        uint32_t lo, hi;
        hi = pack_split_h(o[dt][0] * inv0, o[dt][1] * inv0, lo);
        *(uint32_t*)&Xh[adr0] = hi; *(uint32_t*)&Xl[adr0] = lo;
        hi = pack_split_h(o[dt][2] * inv1, o[dt][3] * inv1, lo);
        *(uint32_t*)&Xh[adr1] = hi; *(uint32_t*)&Xl[adr1] = lo;
    }
}

// ---------------------------------------------------------------------------
extern "C" void kernel_launch(void* const* d_in, const int* in_sizes, int n_in,
                              void* d_out, int out_size)
{
    const float* query  = (const float*)d_in[0];
    const float* key_in = (const float*)d_in[1];
    const float* value  = (const float*)d_in[2];
    const float* Wq = (const float*)d_in[3];
    const float* bq = (const float*)d_in[4];
    const float* Wk = (const float*)d_in[5];
    const float* bk = (const float*)d_in[6];
    const float* Wv = (const float*)d_in[7];
    const float* bv = (const float*)d_in[8];
    const float* Wo = (const float*)d_in[9];
    const float* bo = (const float*)d_in[10];
    float* out = (float*)d_out;

    __half *Qh, *Kh, *Vh, *X1h, *X1l, *X2h, *X3h, *Wth;
    cudaGetSymbolAddress((void**)&Qh, g_Qh);
    cudaGetSymbolAddress((void**)&Kh, g_Kh);
    cudaGetSymbolAddress((void**)&Vh, g_Vh);
    cudaGetSymbolAddress((void**)&X1h, g_X1h);
    cudaGetSymbolAddress((void**)&X1l, g_X1l);
    cudaGetSymbolAddress((void**)&X2h, g_X2h);
    cudaGetSymbolAddress((void**)&X3h, g_X3h);
    cudaGetSymbolAddress((void**)&Wth, g_Wth);

    cudaFuncSetAttribute(qkv_gemm_kernel, cudaFuncAttributeMaxDynamicSharedMemorySize, QKV_SMEM);
    cudaFuncSetAttribute(out_gemm_kernel, cudaFuncAttributeMaxDynamicSharedMemorySize, OUT_SMEM);
    cudaFuncSetAttribute(attn_mma_kernel, cudaFuncAttributeMaxDynamicSharedMemorySize, ATTN_SMEM);

    const int n4 = MROWS * EE / 4;
    const size_t WSZ = (size_t)EE * EE;
    dim3 gt(EE/32, EE/32, 4), bt(32, 32);
    dim3 gs(1024, 3);

    split3_kernel<<<gs, 256>>>(query, key_in, value, X1h, X2h, X3h, n4);
    transpose4_kernel<<<gt, bt>>>(Wq, Wk, Wv, Wo, Wth);

    dim3 gqkv(EE/BN, MROWS/BM, 3);     // (8, 32, 3) = 768 blocks
    qkv_gemm_kernel<<<gqkv, 256, QKV_SMEM>>>(X1h, X2h, X3h, Wth,
                                             bq, bk, bv, Qh, Kh, Vh);

    dim3 ga(SS/AQT, BB*HH);            // (16, 32)
    attn_mma_kernel<<<ga, 256, ATTN_SMEM>>>(Qh, Kh, Vh, X1h, X1l);

    dim3 gg(EE/BN, MROWS/BM);          // (8, 32)
    out_gemm_kernel<<<gg, 256, OUT_SMEM>>>(X1h, X1l, Wth + 3*WSZ, bo, out);
}

// round 15
// speedup vs baseline: 3.7507x; 1.1757x over previous
#include <cuda_runtime.h>
#include <cuda_fp16.h>
#include <cstdint>
#include <math.h>

#define BB 2
#define SS 2048
#define EE 2048
#define HH 16
#define DD 128
#define MROWS (BB*SS)   // 4096

// ---------------- device scratch (fp16) ----------------
__device__ __half g_Qh[MROWS*EE];  // [B*H, S, D] single
__device__ __half g_Kh[MROWS*EE];  // [B*H, S, D] single
__device__ __half g_Vh[MROWS*EE];  // [B*H, D, S] single (transposed)
__device__ __half g_X1h[MROWS*EE]; // query input single / attn-out single
__device__ __half g_X2h[MROWS*EE];
__device__ __half g_X3h[MROWS*EE];
__device__ __half g_Wth[4*EE*EE];  // 4 weights, W^T single fp16 [n][k]

// ---------------- primitives ----------------
__device__ __forceinline__ uint32_t smem_u32(const void* p) {
    uint32_t a;
    asm("{ .reg .u64 t; cvta.to.shared.u64 t, %1; cvt.u32.u64 %0, t; }" : "=r"(a) : "l"(p));
    return a;
}
#define CP_ASYNC_16(dst_u32, src_ptr) \
    asm volatile("cp.async.cg.shared.global [%0], [%1], 16;" :: "r"(dst_u32), "l"(src_ptr))
#define CP_COMMIT() asm volatile("cp.async.commit_group;" ::: "memory")
#define CP_WAIT(n)  asm volatile("cp.async.wait_group %0;" :: "n"(n) : "memory")

__device__ __forceinline__ void mma16816(float* c, const uint32_t* a, const uint32_t* b) {
    asm volatile(
        "mma.sync.aligned.m16n8k16.row.col.f32.f16.f16.f32 "
        "{%0,%1,%2,%3}, {%4,%5,%6,%7}, {%8,%9}, {%0,%1,%2,%3};"
        : "+f"(c[0]), "+f"(c[1]), "+f"(c[2]), "+f"(c[3])
        : "r"(a[0]), "r"(a[1]), "r"(a[2]), "r"(a[3]), "r"(b[0]), "r"(b[1]));
}

__device__ __forceinline__ void ldsm_x4(uint32_t& r0, uint32_t& r1, uint32_t& r2,
                                        uint32_t& r3, uint32_t addr) {
    asm volatile("ldmatrix.sync.aligned.m8n8.x4.shared.b16 {%0,%1,%2,%3}, [%4];"
                 : "=r"(r0), "=r"(r1), "=r"(r2), "=r"(r3) : "r"(addr));
}

__device__ __forceinline__ uint32_t pack2_h(float x, float y) {
    __half2 p; p.x = __float2half_rn(x); p.y = __float2half_rn(y);
    return *(uint32_t*)&p;
}

// ---------------------------------------------------------------------------
// Conversion kernels
// ---------------------------------------------------------------------------
__global__ __launch_bounds__(256)
void split3_kernel(const float* __restrict__ X0, const float* __restrict__ X1,
                   const float* __restrict__ X2,
                   __half* __restrict__ H0, __half* __restrict__ H1,
                   __half* __restrict__ H2, int n4)
{
    const int z = blockIdx.y;
    const float* X = (z == 0) ? X0 : (z == 1) ? X1 : X2;
    __half* H = (z == 0) ? H0 : (z == 1) ? H1 : H2;
    int i = blockIdx.x * blockDim.x + threadIdx.x;
    const int stride = gridDim.x * blockDim.x;
    for (; i < n4; i += stride) {
        float4 v = ((const float4*)X)[i];
        ((uint32_t*)H)[2*i]   = pack2_h(v.x, v.y);
        ((uint32_t*)H)[2*i+1] = pack2_h(v.z, v.w);
    }
}

__global__ __launch_bounds__(1024)
void transpose4_kernel(const float* __restrict__ W0, const float* __restrict__ W1,
                       const float* __restrict__ W2, const float* __restrict__ W3,
                       __half* __restrict__ Th)
{
    __shared__ float t[32][33];
    const int z = blockIdx.z;
    const float* W = (z == 0) ? W0 : (z == 1) ? W1 : (z == 2) ? W2 : W3;
    __half* TH = Th + (size_t)z * EE * EE;
    const int n0 = blockIdx.x * 32, k0 = blockIdx.y * 32;
    const int tx = threadIdx.x, ty = threadIdx.y;
    t[ty][tx] = W[(size_t)(k0 + ty) * EE + n0 + tx];
    __syncthreads();
    TH[(size_t)(n0 + ty) * EE + k0 + tx] = __float2half_rn(t[tx][ty]);
}

// ---------------------------------------------------------------------------
// Shared GEMM geometry (single-term only now)
// ---------------------------------------------------------------------------
#define BM 128
#define BN 256
#define BK 32
#define ROWB 112
#define A_BYTES (BM*ROWB)              // 14336
#define B_BYTES (BN*ROWB)              // 28672
#define STAGE1 (A_BYTES + B_BYTES)     // 43008
#define GEMM_SMEM (2*STAGE1)           // 86016

// ---------------------------------------------------------------------------
// Single-term fp16 GEMM, batched over blockIdx.z.
// z: 0=Q (head-major fp16), 1=K (head-major fp16), 2=V (transposed fp16),
//    3=output projection (fp32 [m][n]).
// ---------------------------------------------------------------------------
__global__ __launch_bounds__(256)
void gemm_all_kernel(const __half* __restrict__ X1h, const __half* __restrict__ X2h,
                     const __half* __restrict__ X3h, const __half* __restrict__ Xo,
                     const __half* __restrict__ Wt,
                     const float* __restrict__ bq, const float* __restrict__ bk,
                     const float* __restrict__ bv, const float* __restrict__ bo,
                     __half* __restrict__ Qh, __half* __restrict__ Kh,
                     __half* __restrict__ Vh, float* __restrict__ Yf, int zbase)
{
    extern __shared__ char sm[];
    const int z = zbase + blockIdx.z;
    const __half* Xh = (z == 0) ? X1h : (z == 1) ? X2h : (z == 2) ? X3h : Xo;
    const __half* Wh = Wt + (size_t)z * EE * EE;
    const float* bias = (z == 0) ? bq : (z == 1) ? bk : (z == 2) ? bv : bo;

    const int tid  = threadIdx.x;
    const int lane = tid & 31;
    const int wid  = tid >> 5;
    const int g    = lane >> 2;
    const int tig  = lane & 3;

    const int m0 = blockIdx.y * BM;
    const int n0 = blockIdx.x * BN;
    const int wm = (wid & 1) * 64;
    const int wn = (wid >> 1) * 64;

    const uint32_t smb = smem_u32(sm);
    const uint32_t lrow = (lane & 15);
    const uint32_t lcol = (lane >> 4) * 16;

    float c[4][8][4];
#pragma unroll
    for (int i = 0; i < 4; i++)
#pragma unroll
        for (int j = 0; j < 8; j++)
#pragma unroll
            for (int q = 0; q < 4; q++) c[i][j][q] = 0.f;

    const __half* srcA = Xh + (size_t)m0*EE;
    const __half* srcB = Wh + (size_t)n0*EE;

    auto load_stage = [&](int s) {
        const int buf = s & 1;
        const uint32_t base = smb + buf * STAGE1;
        const int k0 = s * BK;
        {
            const __half* src = srcA + k0;
#pragma unroll
            for (int i = 0; i < 2; i++) {
                int idx = tid + i * 256;
                int r = idx >> 2, ch = idx & 3;
                CP_ASYNC_16(base + r * ROWB + ch * 16, src + (size_t)r * EE + ch * 8);
            }
        }
        {
            const __half* src = srcB + k0;
            const uint32_t dst0 = base + A_BYTES;
#pragma unroll
            for (int i = 0; i < 4; i++) {
                int idx = tid + i * 256;
                int r = idx >> 2, ch = idx & 3;
                CP_ASYNC_16(dst0 + r * ROWB + ch * 16, src + (size_t)r * EE + ch * 8);
            }
        }
        CP_COMMIT();
    };

    const int NS = EE / BK;   // 64
    load_stage(0);

    for (int s = 0; s < NS; s++) {
        const int buf = s & 1;
        if (s + 1 < NS) { load_stage(s + 1); CP_WAIT(1); }
        else            { CP_WAIT(0); }
        __syncthreads();

        const uint32_t Ah = smb + buf * STAGE1;
        const uint32_t Bh = Ah + A_BYTES;
        const uint32_t abase = Ah + (wm + lrow) * ROWB + lcol;
        const uint32_t bbase = Bh + (wn + lrow) * ROWB + lcol;

#pragma unroll
        for (int kb = 0; kb < BK; kb += 16) {
            const uint32_t kbyte = kb * 2;
            uint32_t ah[4][4], bh[8][2];
#pragma unroll
            for (int mt = 0; mt < 4; mt++)
                ldsm_x4(ah[mt][0], ah[mt][1], ah[mt][2], ah[mt][3],
                        abase + mt * 16 * ROWB + kbyte);
#pragma unroll
            for (int np = 0; np < 4; np++) {
                uint32_t h0, h1, h2, h3;
                ldsm_x4(h0, h1, h2, h3, bbase + np * 16 * ROWB + kbyte);
                bh[2*np][0] = h0; bh[2*np][1] = h2;
                bh[2*np+1][0] = h1; bh[2*np+1][1] = h3;
            }
#pragma unroll
            for (int mt = 0; mt < 4; mt++)
#pragma unroll
                for (int nt = 0; nt < 8; nt++)
                    mma16816(c[mt][nt], ah[mt], bh[nt]);
        }
        __syncthreads();
    }

    // ---- epilogue per z ----
#pragma unroll
    for (int mt = 0; mt < 4; mt++) {
        const int m = m0 + wm + mt * 16 + g;
        const int bI = m >> 11;
        const int sI = m & (SS - 1);
#pragma unroll
        for (int nt = 0; nt < 8; nt++) {
            const int n = n0 + wn + nt * 8 + 2 * tig;
            const float b0 = bias[n], b1 = bias[n + 1];
            const float y0 = c[mt][nt][0] + b0, y1 = c[mt][nt][1] + b1;
            const float y2 = c[mt][nt][2] + b0, y3 = c[mt][nt][3] + b1;
            if (z == 3) {
                size_t o0 = (size_t)m * EE + n;
                float2 v0; v0.x = y0; v0.y = y1;
                float2 v1; v1.x = y2; v1.y = y3;
                *(float2*)&Yf[o0] = v0;
                *(float2*)&Yf[o0 + 8 * EE] = v1;
            } else {
                const int h = n >> 7, d = n & 127;
                if (z != 2) {
                    __half* Yh = (z == 0) ? Qh : Kh;
                    size_t o0 = (((size_t)(bI * HH + h) * SS + sI) * DD) + d;
                    *(uint32_t*)&Yh[o0] = pack2_h(y0, y1);
                    *(uint32_t*)&Yh[o0 + 8 * DD] = pack2_h(y2, y3);
                } else {
                    const size_t base = (size_t)(bI * HH + h) * DD;
                    size_t o00 = (base + d) * SS + sI;
                    size_t o01 = (base + d + 1) * SS + sI;
                    Vh[o00]     = __float2half_rn(y0);
                    Vh[o01]     = __float2half_rn(y1);
                    Vh[o00 + 8] = __float2half_rn(y2);
                    Vh[o01 + 8] = __float2half_rn(y3);
                }
            }
        }
    }
}

// ---------------------------------------------------------------------------
// Flash attention: Q/K/V single fp16, single-term QK and PV; single fp16 out.
// ---------------------------------------------------------------------------
#define AQT 128
#define AKT 64
#define ROWK 272
#define ROWV 144
#define KH_BYTES (64*ROWK)          // 17408
#define VH_BYTES (128*ROWV)         // 18432
#define KV_STAGE (KH_BYTES + VH_BYTES)   // 35840
#define ATTN_SMEM (2*KV_STAGE)           // 71680

__global__ __launch_bounds__(256)
void attn_mma_kernel(const __half* __restrict__ Qh_, const __half* __restrict__ Kh_,
                     const __half* __restrict__ Vh_, __half* __restrict__ Xh)
{
    extern __shared__ char sm[];
    const uint32_t smb = smem_u32(sm);
    const int tid  = threadIdx.x;
    const int lane = tid & 31;
    const int wid  = tid >> 5;
    const int g    = lane >> 2;
    const int tig  = lane & 3;
    const uint32_t lrow = (lane & 15);
    const uint32_t lcol = (lane >> 4) * 16;

    const int bh = blockIdx.y;
    const int q0 = blockIdx.x * AQT;
    const size_t hoff = (size_t)bh * SS * DD;

    const __half* ksrc = Kh_ + hoff;
    const __half* vsrc = Vh_ + (size_t)bh * DD * SS;

    // ---- Q tile (single) to smem, fragments via ldmatrix ----
    {
        const __half* qsrc = Qh_ + hoff + (size_t)q0 * DD;
#pragma unroll
        for (int i = 0; i < 8; i++) {
            int idx = tid + i * 256;
            int row = idx >> 4, ch = idx & 15;
            CP_ASYNC_16(smb + row * ROWK + ch * 16, qsrc + (size_t)row * DD + ch * 8);
        }
        CP_COMMIT(); CP_WAIT(0);
        __syncthreads();
    }

    uint32_t qh[8][4];
    {
        const uint32_t ro = (wid * 16 + lrow) * ROWK + lcol;
#pragma unroll
        for (int ks = 0; ks < 8; ks++)
            ldsm_x4(qh[ks][0], qh[ks][1], qh[ks][2], qh[ks][3], smb + ro + ks * 32);
    }
    __syncthreads();

    auto load_kv = [&](int it) {
        const uint32_t base = smb + (it & 1) * KV_STAGE;
        const int kt = it * AKT;
#pragma unroll
        for (int i = 0; i < 4; i++) {
            int idx = tid + i * 256;
            int row = idx >> 4, ch = idx & 15;
            CP_ASYNC_16(base + row * ROWK + ch * 16,
                        ksrc + (size_t)(kt + row) * DD + ch * 8);
        }
        {
            const uint32_t dst0 = base + KH_BYTES;
#pragma unroll
            for (int i = 0; i < 4; i++) {
                int idx = tid + i * 256;
                int row = idx >> 3, ch = idx & 7;
                CP_ASYNC_16(dst0 + row * ROWV + ch * 16,
                            vsrc + (size_t)row * SS + kt + ch * 8);
            }
        }
        CP_COMMIT();
    };

    const float scale = 0.08838834764831845f;
    float m0 = -INFINITY, m1 = -INFINITY, l0 = 0.f, l1 = 0.f;
    float o[16][4];
#pragma unroll
    for (int dt = 0; dt < 16; dt++)
#pragma unroll
        for (int q = 0; q < 4; q++) o[dt][q] = 0.f;

    const int NIT = SS / AKT;
    load_kv(0);

    for (int it = 0; it < NIT; it++) {
        if (it + 1 < NIT) { load_kv(it + 1); CP_WAIT(1); }
        else              { CP_WAIT(0); }
        __syncthreads();

        const uint32_t smK = smb + (it & 1) * KV_STAGE;
        const uint32_t smV = smK + KH_BYTES;
        const uint32_t kbase = smK + lrow * ROWK + lcol;   // hoisted LDSM bases
        const uint32_t vbase = smV + lrow * ROWV + lcol;

        // ---- scores: single-term Q x K ----
        float sc[8][4];
#pragma unroll
        for (int nt = 0; nt < 8; nt++)
#pragma unroll
            for (int q = 0; q < 4; q++) sc[nt][q] = 0.f;

#pragma unroll
        for (int ks = 0; ks < 8; ks++) {
#pragma unroll
            for (int np = 0; np < 4; np++) {
                uint32_t h0, h1, h2, h3;
                ldsm_x4(h0, h1, h2, h3, kbase + np * (16 * ROWK) + ks * 32);
                uint32_t b0h[2] = { h0, h2 }, b1h[2] = { h1, h3 };
                mma16816(sc[2*np],   qh[ks], b0h);
                mma16816(sc[2*np+1], qh[ks], b1h);
            }
        }

        // ---- online softmax ----
        float mx0 = -INFINITY, mx1 = -INFINITY;
#pragma unroll
        for (int nt = 0; nt < 8; nt++) {
            mx0 = fmaxf(mx0, fmaxf(sc[nt][0], sc[nt][1]));
            mx1 = fmaxf(mx1, fmaxf(sc[nt][2], sc[nt][3]));
        }
        mx0 = fmaxf(mx0, __shfl_xor_sync(0xffffffffu, mx0, 1));
        mx0 = fmaxf(mx0, __shfl_xor_sync(0xffffffffu, mx0, 2));
        mx1 = fmaxf(mx1, __shfl_xor_sync(0xffffffffu, mx1, 1));
        mx1 = fmaxf(mx1, __shfl_xor_sync(0xffffffffu, mx1, 2));

        const float mn0 = fmaxf(m0, mx0 * scale);
        const float mn1 = fmaxf(m1, mx1 * scale);
        const float a0 = __expf(m0 - mn0);
        const float a1 = __expf(m1 - mn1);
        m0 = mn0; m1 = mn1;

        float rs0 = 0.f, rs1 = 0.f;
        uint32_t ph[8][2];
#pragma unroll
        for (int nt = 0; nt < 8; nt++) {
            float p0 = __expf(sc[nt][0] * scale - mn0);
            float p1 = __expf(sc[nt][1] * scale - mn0);
            float p2 = __expf(sc[nt][2] * scale - mn1);
            float p3 = __expf(sc[nt][3] * scale - mn1);
            rs0 += p0 + p1; rs1 += p2 + p3;
            ph[nt][0] = pack2_h(p0, p1);
            ph[nt][1] = pack2_h(p2, p3);
        }
        rs0 += __shfl_xor_sync(0xffffffffu, rs0, 1);
        rs0 += __shfl_xor_sync(0xffffffffu, rs0, 2);
        rs1 += __shfl_xor_sync(0xffffffffu, rs1, 1);
        rs1 += __shfl_xor_sync(0xffffffffu, rs1, 2);
        l0 = l0 * a0 + rs0;
        l1 = l1 * a1 + rs1;

#pragma unroll
        for (int dt = 0; dt < 16; dt++) {
            o[dt][0] *= a0; o[dt][1] *= a0;
            o[dt][2] *= a1; o[dt][3] *= a1;
        }

        // ---- PV: single-term P x V ----
#pragma unroll
        for (int ks = 0; ks < 4; ks++) {
            uint32_t ah[4] = { ph[2*ks][0], ph[2*ks][1], ph[2*ks+1][0], ph[2*ks+1][1] };
#pragma unroll
            for (int dp = 0; dp < 8; dp++) {
                uint32_t h0, h1, h2, h3;
                ldsm_x4(h0, h1, h2, h3, vbase + dp * (16 * ROWV) + ks * 32);
                uint32_t b0h[2] = { h0, h2 }, b1h[2] = { h1, h3 };
                mma16816(o[2*dp],   ah, b0h);
                mma16816(o[2*dp+1], ah, b1h);
            }
        }
        __syncthreads();
    }

    // ---- epilogue: normalize, single fp16, store ----
    const float inv0 = 1.0f / l0;
    const float inv1 = 1.0f / l1;
    const int bI = bh >> 4;
    const int h  = bh & 15;
    const int row0 = q0 + wid * 16 + g;
#pragma unroll
    for (int dt = 0; dt < 16; dt++) {
        const int e = h * 128 + dt * 8 + 2 * tig;
        size_t adr0 = (size_t)(bI * SS + row0) * EE + e;
        size_t adr1 = adr0 + (size_t)8 * EE;
        *(uint32_t*)&Xh[adr0] = pack2_h(o[dt][0] * inv0, o[dt][1] * inv0);
        *(uint32_t*)&Xh[adr1] = pack2_h(o[dt][2] * inv1, o[dt][3] * inv1);
    }
}

// ---------------------------------------------------------------------------
extern "C" void kernel_launch(void* const* d_in, const int* in_sizes, int n_in,
                              void* d_out, int out_size)
{
    const float* query  = (const float*)d_in[0];
    const float* key_in = (const float*)d_in[1];
    const float* value  = (const float*)d_in[2];
    const float* Wq = (const float*)d_in[3];
    const float* bq = (const float*)d_in[4];
    const float* Wk = (const float*)d_in[5];
    const float* bk = (const float*)d_in[6];
    const float* Wv = (const float*)d_in[7];
    const float* bv = (const float*)d_in[8];
    const float* Wo = (const float*)d_in[9];
    const float* bo = (const float*)d_in[10];
    float* out = (float*)d_out;

    __half *Qh, *Kh, *Vh, *X1h, *X2h, *X3h, *Wth;
    cudaGetSymbolAddress((void**)&Qh, g_Qh);
    cudaGetSymbolAddress((void**)&Kh, g_Kh);
    cudaGetSymbolAddress((void**)&Vh, g_Vh);
    cudaGetSymbolAddress((void**)&X1h, g_X1h);
    cudaGetSymbolAddress((void**)&X2h, g_X2h);
    cudaGetSymbolAddress((void**)&X3h, g_X3h);
    cudaGetSymbolAddress((void**)&Wth, g_Wth);

    cudaFuncSetAttribute(gemm_all_kernel, cudaFuncAttributeMaxDynamicSharedMemorySize, GEMM_SMEM);
    cudaFuncSetAttribute(attn_mma_kernel, cudaFuncAttributeMaxDynamicSharedMemorySize, ATTN_SMEM);

    const int n4 = MROWS * EE / 4;
    dim3 gt(EE/32, EE/32, 4), bt(32, 32);
    dim3 gs(1024, 3);

    split3_kernel<<<gs, 256>>>(query, key_in, value, X1h, X2h, X3h, n4);
    transpose4_kernel<<<gt, bt>>>(Wq, Wk, Wv, Wo, Wth);

    // batched Q/K/V projections (z = 0,1,2)
    dim3 gqkv(EE/BN, MROWS/BM, 3);     // (8, 32, 3) = 768 blocks
    gemm_all_kernel<<<gqkv, 256, GEMM_SMEM>>>(X1h, X2h, X3h, nullptr, Wth,
                                              bq, bk, bv, bo, Qh, Kh, Vh, nullptr, 0);

    // attention -> X1h (single fp16)
    dim3 ga(SS/AQT, BB*HH);            // (16, 32)
    attn_mma_kernel<<<ga, 256, ATTN_SMEM>>>(Qh, Kh, Vh, X1h);

    // output projection (z = 3), fp32 out
    dim3 gg(EE/BN, MROWS/BM, 1);       // (8, 32)
    gemm_all_kernel<<<gg, 256, GEMM_SMEM>>>(nullptr, nullptr, nullptr, X1h, Wth,
                                            bq, bk, bv, bo, nullptr, nullptr, nullptr, out, 3);
}